// round 2
// baseline (speedup 1.0000x reference)
#include <cuda_runtime.h>
#include <math.h>
#include <stdint.h>

// Problem constants
#define BB   4
#define HH   16
#define LL   2048
#define DD   1024
#define DH   64
#define MM   (BB*LL)   // 8192 tokens

// Scratch (device globals: allocation-free, graph-capturable)
__device__ float g_q[(size_t)BB*HH*LL*DH];    // (B,H,L,dh)
__device__ float g_k[(size_t)BB*HH*LL*DH];
__device__ float g_v[(size_t)BB*HH*LL*DH];
__device__ float g_ctx[(size_t)MM*DD];        // (B,L,D) attention output

// ---------------------------------------------------------------------------
// SGEMM: out[m,n] = sum_k A[m,k]*W[n,k] + bias[n]
// Both A and W are row-major with K contiguous (torch Linear convention).
// mode 0/1/2: A=Aext(x), out=g_q/g_k/g_v with (B,H,L,dh) remap epilogue
// mode 3    : A=g_ctx,   out=Oext, plain (M,N) layout
// Tile: 128x128, K-step 8, 256 threads, 8x8 per thread.
// ---------------------------------------------------------------------------
__global__ void __launch_bounds__(256) sgemm_kernel(
    const float* __restrict__ Aext,
    const float* __restrict__ W,
    const float* __restrict__ bias,
    float* __restrict__ Oext,
    int mode)
{
    const float* A = (mode == 3) ? g_ctx : Aext;
    float* out = (mode == 0) ? g_q : (mode == 1) ? g_k : (mode == 2) ? g_v : Oext;

    __shared__ float As[8][128];
    __shared__ float Bs[8][128];

    const int tid  = threadIdx.x;
    const int bm   = blockIdx.y * 128;
    const int bn   = blockIdx.x * 128;
    const int lrow = tid >> 1;            // 0..127
    const int lcol = (tid & 1) * 4;       // 0 or 4
    const float* Aptr = A + (size_t)(bm + lrow) * DD + lcol;
    const float* Wptr = W + (size_t)(bn + lrow) * DD + lcol;
    const int wy = tid >> 4;              // 0..15 -> rows wy*8..wy*8+7
    const int wx = tid & 15;              // 0..15 -> cols wx*8..wx*8+7

    float acc[8][8];
    #pragma unroll
    for (int i = 0; i < 8; i++)
        #pragma unroll
        for (int j = 0; j < 8; j++) acc[i][j] = 0.f;

    for (int k0 = 0; k0 < DD; k0 += 8) {
        float4 av = *(const float4*)(Aptr + k0);
        float4 wv = *(const float4*)(Wptr + k0);
        __syncthreads();   // previous iteration's reads complete
        As[lcol+0][lrow] = av.x; As[lcol+1][lrow] = av.y;
        As[lcol+2][lrow] = av.z; As[lcol+3][lrow] = av.w;
        Bs[lcol+0][lrow] = wv.x; Bs[lcol+1][lrow] = wv.y;
        Bs[lcol+2][lrow] = wv.z; Bs[lcol+3][lrow] = wv.w;
        __syncthreads();

        #pragma unroll
        for (int kk = 0; kk < 8; kk++) {
            float4 a0 = *(const float4*)&As[kk][wy*8];
            float4 a1 = *(const float4*)&As[kk][wy*8+4];
            float4 b0 = *(const float4*)&Bs[kk][wx*8];
            float4 b1 = *(const float4*)&Bs[kk][wx*8+4];
            float ar[8] = {a0.x,a0.y,a0.z,a0.w,a1.x,a1.y,a1.z,a1.w};
            float br[8] = {b0.x,b0.y,b0.z,b0.w,b1.x,b1.y,b1.z,b1.w};
            #pragma unroll
            for (int i = 0; i < 8; i++)
                #pragma unroll
                for (int j = 0; j < 8; j++)
                    acc[i][j] += ar[i] * br[j];
        }
    }

    #pragma unroll
    for (int i = 0; i < 8; i++) {
        const int m  = bm + wy*8 + i;
        const int bb = m >> 11;           // token -> batch
        const int ll = m & (LL - 1);      // token -> seq pos
        #pragma unroll
        for (int jj = 0; jj < 8; jj += 4) {
            const int n = bn + wx*8 + jj;
            float4 r;
            r.x = acc[i][jj+0] + bias[n+0];
            r.y = acc[i][jj+1] + bias[n+1];
            r.z = acc[i][jj+2] + bias[n+2];
            r.w = acc[i][jj+3] + bias[n+3];
            if (mode <= 2) {
                const int h = n >> 6;
                const int c = n & (DH - 1);
                *(float4*)&out[(((size_t)(bb*HH + h) * LL) + ll) * DH + c] = r;
            } else {
                *(float4*)&out[(size_t)m * DD + n] = r;
            }
        }
    }
}

// ---------------------------------------------------------------------------
// Flash attention: per block one (b,h) and 64 queries; iterate 32 key tiles
// of 64. Online softmax. 256 threads, each owns a 4x4 fragment.
// Shared: Qt[d][m] (16KB), KP (Kt[d][n], then reused for P[m][key]) (16KB),
// Vs[key][c] (16KB) = 48KB static.
// Mask is int32 (harness promotes bool -> int32): nonzero = masked key.
// ---------------------------------------------------------------------------
__global__ void __launch_bounds__(256) attn_kernel(const int* __restrict__ mask)
{
    __shared__ float Qt[64][64];   // [d][m]
    __shared__ float KP[64][64];   // Kt[d][n] -> P[m][key]
    __shared__ float Vs[64][64];   // [key][c]

    const int qt  = blockIdx.x;    // 0..31
    const int h   = blockIdx.y;    // 0..15
    const int b   = blockIdx.z;    // 0..3
    const int tid = threadIdx.x;
    const int ty  = tid >> 4;      // 0..15 -> query rows ty*4..+3
    const int tx  = tid & 15;      // 0..15 -> key cols / dh cols tx*4..+3

    const size_t headoff = ((size_t)(b*HH + h)) * LL * DH;
    const float* qbase = g_q + headoff;
    const float* kbase = g_k + headoff;
    const float* vbase = g_v + headoff;
    const int l0 = qt * 64;

    // Load Q tile transposed: Qt[c][m]
    #pragma unroll
    for (int rep = 0; rep < 4; rep++) {
        int idx = rep*256 + tid;
        int r   = idx >> 4;
        int c4  = (idx & 15) * 4;
        float4 qv = *(const float4*)(qbase + (size_t)(l0 + r)*DH + c4);
        Qt[c4+0][r] = qv.x; Qt[c4+1][r] = qv.y;
        Qt[c4+2][r] = qv.z; Qt[c4+3][r] = qv.w;
    }

    float o[4][4];
    #pragma unroll
    for (int i = 0; i < 4; i++)
        #pragma unroll
        for (int j = 0; j < 4; j++) o[i][j] = 0.f;
    float mi[4], li[4];
    #pragma unroll
    for (int i = 0; i < 4; i++) { mi[i] = -INFINITY; li[i] = 0.f; }

    for (int kt = 0; kt < 32; kt++) {
        const int k0 = kt * 64;
        __syncthreads();   // previous PV reads of KP/Vs done (and Q stores on iter 0)

        // Load K transposed (Kt[d][n]) and V natural (Vs[key][c])
        #pragma unroll
        for (int rep = 0; rep < 4; rep++) {
            int idx = rep*256 + tid;
            int r   = idx >> 4;
            int c4  = (idx & 15) * 4;
            float4 kv = *(const float4*)(kbase + (size_t)(k0 + r)*DH + c4);
            KP[c4+0][r] = kv.x; KP[c4+1][r] = kv.y;
            KP[c4+2][r] = kv.z; KP[c4+3][r] = kv.w;
            float4 vv = *(const float4*)(vbase + (size_t)(k0 + r)*DH + c4);
            *(float4*)&Vs[r][c4] = vv;
        }
        __syncthreads();

        // S = Q K^T (4x4 fragment per thread)
        float s[4][4];
        #pragma unroll
        for (int i = 0; i < 4; i++)
            #pragma unroll
            for (int j = 0; j < 4; j++) s[i][j] = 0.f;

        #pragma unroll 16
        for (int d = 0; d < 64; d++) {
            float4 q4 = *(const float4*)&Qt[d][ty*4];
            float4 k4 = *(const float4*)&KP[d][tx*4];
            float qa[4] = {q4.x,q4.y,q4.z,q4.w};
            float ka[4] = {k4.x,k4.y,k4.z,k4.w};
            #pragma unroll
            for (int i = 0; i < 4; i++)
                #pragma unroll
                for (int j = 0; j < 4; j++)
                    s[i][j] += qa[i] * ka[j];
        }

        // scale + mask (exact -1e9 like the reference). Mask is int32.
        int4 mv = *(const int4*)(mask + (size_t)b*LL + k0 + tx*4);
        int mraw[4] = {mv.x, mv.y, mv.z, mv.w};
        #pragma unroll
        for (int i = 0; i < 4; i++)
            #pragma unroll
            for (int j = 0; j < 4; j++)
                s[i][j] = mraw[j] ? -1e9f : s[i][j] * 0.125f;

        // online softmax update
        #pragma unroll
        for (int i = 0; i < 4; i++) {
            float rm = fmaxf(fmaxf(s[i][0], s[i][1]), fmaxf(s[i][2], s[i][3]));
            #pragma unroll
            for (int off = 8; off >= 1; off >>= 1)
                rm = fmaxf(rm, __shfl_xor_sync(0xffffffffu, rm, off, 16));
            float newm = fmaxf(mi[i], rm);
            float corr = __expf(mi[i] - newm);
            float rs = 0.f;
            #pragma unroll
            for (int j = 0; j < 4; j++) {
                s[i][j] = __expf(s[i][j] - newm);
                rs += s[i][j];
            }
            #pragma unroll
            for (int off = 8; off >= 1; off >>= 1)
                rs += __shfl_xor_sync(0xffffffffu, rs, off, 16);
            li[i] = li[i] * corr + rs;
            mi[i] = newm;
            #pragma unroll
            for (int j = 0; j < 4; j++) o[i][j] *= corr;
        }

        __syncthreads();   // everyone done reading K from KP
        // store P row-major: P[m][key]
        #pragma unroll
        for (int i = 0; i < 4; i++)
            *(float4*)&KP[ty*4+i][tx*4] = make_float4(s[i][0], s[i][1], s[i][2], s[i][3]);
        __syncthreads();

        // O += P @ V
        #pragma unroll 16
        for (int kk = 0; kk < 64; kk++) {
            float4 v4 = *(const float4*)&Vs[kk][tx*4];
            float va[4] = {v4.x,v4.y,v4.z,v4.w};
            float pr[4];
            #pragma unroll
            for (int i = 0; i < 4; i++) pr[i] = KP[ty*4+i][kk];
            #pragma unroll
            for (int i = 0; i < 4; i++)
                #pragma unroll
                for (int j = 0; j < 4; j++)
                    o[i][j] += pr[i] * va[j];
        }
    }

    // epilogue: normalize and write ctx in (B,L,D) layout
    #pragma unroll
    for (int i = 0; i < 4; i++) {
        float inv = 1.f / li[i];
        int lrow = l0 + ty*4 + i;
        float4 r = make_float4(o[i][0]*inv, o[i][1]*inv, o[i][2]*inv, o[i][3]*inv);
        *(float4*)&g_ctx[((size_t)(b*LL + lrow)) * DD + h*DH + tx*4] = r;
    }
}

// ---------------------------------------------------------------------------
extern "C" void kernel_launch(void* const* d_in, const int* in_sizes, int n_in,
                              void* d_out, int out_size)
{
    const float* x  = (const float*)d_in[0];
    const int* mask = (const int*)d_in[1];
    const float* wq = (const float*)d_in[2];
    const float* bq = (const float*)d_in[3];
    const float* wk = (const float*)d_in[4];
    const float* bk = (const float*)d_in[5];
    const float* wv = (const float*)d_in[6];
    const float* bv = (const float*)d_in[7];
    const float* wo = (const float*)d_in[8];
    const float* bo = (const float*)d_in[9];
    float* out = (float*)d_out;

    dim3 gg(DD/128, MM/128);   // 8 x 64 blocks
    sgemm_kernel<<<gg, 256>>>(x, wq, bq, nullptr, 0);
    sgemm_kernel<<<gg, 256>>>(x, wk, bk, nullptr, 1);
    sgemm_kernel<<<gg, 256>>>(x, wv, bv, nullptr, 2);

    dim3 ga(LL/64, HH, BB);    // 32 x 16 x 4 blocks
    attn_kernel<<<ga, 256>>>(mask);

    sgemm_kernel<<<gg, 256>>>(nullptr, wo, bo, out, 3);
}

// round 3
// speedup vs baseline: 2.6972x; 2.6972x over previous
#include <cuda_runtime.h>
#include <math.h>
#include <stdint.h>

// Problem constants
#define BB   4
#define HH   16
#define LL   2048
#define DD   1024
#define DH   64
#define MM   (BB*LL)   // 8192 tokens

// Scratch (device globals: allocation-free, graph-capturable)
__device__ float g_q[(size_t)BB*HH*LL*DH];    // (B,H,L,dh)
__device__ float g_k[(size_t)BB*HH*LL*DH];
__device__ float g_v[(size_t)BB*HH*LL*DH];
__device__ float g_ctx[(size_t)MM*DD];        // (B,L,D) attention output

__device__ __forceinline__ uint32_t f2tf(float f) {
    uint32_t u;
    asm("cvt.rna.tf32.f32 %0, %1;" : "=r"(u) : "f"(f));
    return u;
}

__device__ __forceinline__ void mma_tf32(float c[4], const uint32_t a[4],
                                         uint32_t b0, uint32_t b1) {
    asm volatile(
        "mma.sync.aligned.m16n8k8.row.col.f32.tf32.tf32.f32 "
        "{%0,%1,%2,%3}, {%4,%5,%6,%7}, {%8,%9}, {%0,%1,%2,%3};"
        : "+f"(c[0]), "+f"(c[1]), "+f"(c[2]), "+f"(c[3])
        : "r"(a[0]), "r"(a[1]), "r"(a[2]), "r"(a[3]), "r"(b0), "r"(b1));
}

// ---------------------------------------------------------------------------
// tf32 tensor-core GEMM: out[m,n] = sum_k A[m,k]*W[n,k] + bias[n]
// Tile 128x128, BK=16, 256 threads (8 warps as 2x4; each warp 64x32).
// mode 0/1/2: A=x, out=g_q/g_k/g_v with (B,H,L,dh) remap; mode 3: g_ctx->out.
// ---------------------------------------------------------------------------
__global__ void __launch_bounds__(256) gemm_tf32(
    const float* __restrict__ Aext,
    const float* __restrict__ W,
    const float* __restrict__ bias,
    float* __restrict__ Oext,
    int mode)
{
    const float* A = (mode == 3) ? g_ctx : Aext;
    float* out = (mode == 0) ? g_q : (mode == 1) ? g_k : (mode == 2) ? g_v : Oext;

    __shared__ uint32_t As[128][20];   // [m][k], pad 4
    __shared__ uint32_t Ws[128][20];   // [n][k], pad 4

    const int tid  = threadIdx.x;
    const int wid  = tid >> 5;
    const int lane = tid & 31;
    const int gid  = lane >> 2;   // 0..7
    const int tig  = lane & 3;    // 0..3
    const int warp_m = (wid & 1) * 64;
    const int warp_n = (wid >> 1) * 32;
    const int bm = blockIdx.y * 128;
    const int bn = blockIdx.x * 128;

    const int lrow = tid >> 1;          // 0..127
    const int lc4  = (tid & 1) * 4;     // 0 or 4 (+8 for 2nd vec)

    const float* Arow = A + (size_t)(bm + lrow) * DD;
    const float* Wrow = W + (size_t)(bn + lrow) * DD;

    float acc[4][4][4];
    #pragma unroll
    for (int mt = 0; mt < 4; mt++)
        #pragma unroll
        for (int nt = 0; nt < 4; nt++)
            #pragma unroll
            for (int r = 0; r < 4; r++) acc[mt][nt][r] = 0.f;

    for (int k0 = 0; k0 < DD; k0 += 16) {
        float4 a0 = *(const float4*)(Arow + k0 + lc4);
        float4 a1 = *(const float4*)(Arow + k0 + lc4 + 8);
        float4 w0 = *(const float4*)(Wrow + k0 + lc4);
        float4 w1 = *(const float4*)(Wrow + k0 + lc4 + 8);
        __syncthreads();   // previous iter's frag reads done
        {
            uint4 u;
            u.x = f2tf(a0.x); u.y = f2tf(a0.y); u.z = f2tf(a0.z); u.w = f2tf(a0.w);
            *(uint4*)&As[lrow][lc4] = u;
            u.x = f2tf(a1.x); u.y = f2tf(a1.y); u.z = f2tf(a1.z); u.w = f2tf(a1.w);
            *(uint4*)&As[lrow][lc4 + 8] = u;
            u.x = f2tf(w0.x); u.y = f2tf(w0.y); u.z = f2tf(w0.z); u.w = f2tf(w0.w);
            *(uint4*)&Ws[lrow][lc4] = u;
            u.x = f2tf(w1.x); u.y = f2tf(w1.y); u.z = f2tf(w1.z); u.w = f2tf(w1.w);
            *(uint4*)&Ws[lrow][lc4 + 8] = u;
        }
        __syncthreads();

        #pragma unroll
        for (int ks = 0; ks < 2; ks++) {
            const int kb = ks * 8;
            uint32_t bf[4][2];
            #pragma unroll
            for (int nt = 0; nt < 4; nt++) {
                const int n = warp_n + nt*8 + gid;
                bf[nt][0] = Ws[n][kb + tig];
                bf[nt][1] = Ws[n][kb + tig + 4];
            }
            #pragma unroll
            for (int mt = 0; mt < 4; mt++) {
                const int m = warp_m + mt*16;
                uint32_t af[4];
                af[0] = As[m + gid    ][kb + tig];
                af[1] = As[m + gid + 8][kb + tig];
                af[2] = As[m + gid    ][kb + tig + 4];
                af[3] = As[m + gid + 8][kb + tig + 4];
                #pragma unroll
                for (int nt = 0; nt < 4; nt++)
                    mma_tf32(acc[mt][nt], af, bf[nt][0], bf[nt][1]);
            }
        }
    }

    // epilogue
    #pragma unroll
    for (int mt = 0; mt < 4; mt++) {
        #pragma unroll
        for (int nt = 0; nt < 4; nt++) {
            const int col = bn + warp_n + nt*8 + tig*2;
            const float b0 = bias[col], b1 = bias[col + 1];
            #pragma unroll
            for (int half = 0; half < 2; half++) {
                const int m = bm + warp_m + mt*16 + gid + half*8;
                float2 v;
                v.x = acc[mt][nt][half*2 + 0] + b0;
                v.y = acc[mt][nt][half*2 + 1] + b1;
                if (mode <= 2) {
                    const int bb = m >> 11;
                    const int ll = m & (LL - 1);
                    const int h  = col >> 6;
                    const int c  = col & (DH - 1);
                    *(float2*)&out[(((size_t)(bb*HH + h) * LL) + ll) * DH + c] = v;
                } else {
                    *(float2*)&out[(size_t)m * DD + col] = v;
                }
            }
        }
    }
}

// ---------------------------------------------------------------------------
// tf32 flash attention: block = one (b,h,64-query tile), 128 threads (4 warps,
// each owns 16 q rows). 32 key tiles of 64. Online softmax on MMA C-fragments
// (quad shuffles). P round-trips through smem (reuses K buffer) for PV MMA.
// ---------------------------------------------------------------------------
__global__ void __launch_bounds__(128) attn_tf32(const int* __restrict__ mask)
{
    __shared__ uint32_t Qs[64][68];   // [q row][d]  pad 4
    __shared__ uint32_t KP[64][68];   // K: [key][d] -> P: [q row][key]
    __shared__ uint32_t Vs[64][72];   // [key][d]    pad 8
    __shared__ int msk[64];

    const int qt  = blockIdx.x;    // 0..31
    const int h   = blockIdx.y;    // 0..15
    const int b   = blockIdx.z;    // 0..3
    const int tid = threadIdx.x;
    const int wid = tid >> 5;      // 0..3
    const int lane = tid & 31;
    const int gid = lane >> 2;     // 0..7
    const int tig = lane & 3;      // 0..3
    const int m0  = wid * 16;      // warp's q-row base within tile

    const size_t headoff = ((size_t)(b*HH + h)) * LL * DH;
    const float* qb = g_q + headoff + (size_t)qt * 64 * DH;
    const float* kb = g_k + headoff;
    const float* vb = g_v + headoff;

    // load + convert Q tile (64x64)
    #pragma unroll
    for (int rep = 0; rep < 8; rep++) {
        const int idx = rep*128 + tid;
        const int r   = idx >> 4;
        const int c4  = (idx & 15) * 4;
        float4 q = *(const float4*)(qb + r*DH + c4);
        Qs[r][c4+0] = f2tf(q.x); Qs[r][c4+1] = f2tf(q.y);
        Qs[r][c4+2] = f2tf(q.z); Qs[r][c4+3] = f2tf(q.w);
    }

    float accO[8][4];
    #pragma unroll
    for (int nt = 0; nt < 8; nt++)
        #pragma unroll
        for (int r = 0; r < 4; r++) accO[nt][r] = 0.f;
    float mi[2] = {-INFINITY, -INFINITY};
    float li[2] = {0.f, 0.f};

    for (int kt = 0; kt < 32; kt++) {
        const float* kbt = kb + (size_t)kt * 64 * DH;
        const float* vbt = vb + (size_t)kt * 64 * DH;
        __syncthreads();   // prev iter's PV reads done (and Q stores on iter 0)

        #pragma unroll
        for (int rep = 0; rep < 8; rep++) {
            const int idx = rep*128 + tid;
            const int r   = idx >> 4;
            const int c4  = (idx & 15) * 4;
            float4 k4 = *(const float4*)(kbt + r*DH + c4);
            KP[r][c4+0] = f2tf(k4.x); KP[r][c4+1] = f2tf(k4.y);
            KP[r][c4+2] = f2tf(k4.z); KP[r][c4+3] = f2tf(k4.w);
            float4 v4 = *(const float4*)(vbt + r*DH + c4);
            Vs[r][c4+0] = f2tf(v4.x); Vs[r][c4+1] = f2tf(v4.y);
            Vs[r][c4+2] = f2tf(v4.z); Vs[r][c4+3] = f2tf(v4.w);
        }
        if (tid < 16) {
            int4 mm = *(const int4*)(mask + (size_t)b*LL + kt*64 + tid*4);
            msk[tid*4+0] = mm.x; msk[tid*4+1] = mm.y;
            msk[tid*4+2] = mm.z; msk[tid*4+3] = mm.w;
        }
        __syncthreads();

        // S = Q K^T : s[nt][.] covers keys nt*8..nt*8+7
        float s[8][4];
        #pragma unroll
        for (int nt = 0; nt < 8; nt++)
            #pragma unroll
            for (int r = 0; r < 4; r++) s[nt][r] = 0.f;

        #pragma unroll
        for (int ks = 0; ks < 8; ks++) {
            const int kb8 = ks * 8;
            uint32_t af[4];
            af[0] = Qs[m0 + gid    ][kb8 + tig];
            af[1] = Qs[m0 + gid + 8][kb8 + tig];
            af[2] = Qs[m0 + gid    ][kb8 + tig + 4];
            af[3] = Qs[m0 + gid + 8][kb8 + tig + 4];
            #pragma unroll
            for (int nt = 0; nt < 8; nt++) {
                uint32_t b0 = KP[nt*8 + gid][kb8 + tig];
                uint32_t b1 = KP[nt*8 + gid][kb8 + tig + 4];
                mma_tf32(s[nt], af, b0, b1);
            }
        }

        // scale + mask (exact -1e9 like reference)
        #pragma unroll
        for (int nt = 0; nt < 8; nt++) {
            const int c0 = nt*8 + tig*2;
            const int mm0 = msk[c0], mm1 = msk[c0+1];
            s[nt][0] = mm0 ? -1e9f : s[nt][0] * 0.125f;
            s[nt][1] = mm1 ? -1e9f : s[nt][1] * 0.125f;
            s[nt][2] = mm0 ? -1e9f : s[nt][2] * 0.125f;
            s[nt][3] = mm1 ? -1e9f : s[nt][3] * 0.125f;
        }

        // online softmax per row half (rows gid and gid+8)
        #pragma unroll
        for (int half = 0; half < 2; half++) {
            float rm = -INFINITY;
            #pragma unroll
            for (int nt = 0; nt < 8; nt++)
                rm = fmaxf(rm, fmaxf(s[nt][half*2], s[nt][half*2+1]));
            rm = fmaxf(rm, __shfl_xor_sync(0xffffffffu, rm, 1));
            rm = fmaxf(rm, __shfl_xor_sync(0xffffffffu, rm, 2));
            const float newm = fmaxf(mi[half], rm);
            const float corr = __expf(mi[half] - newm);
            float rs = 0.f;
            #pragma unroll
            for (int nt = 0; nt < 8; nt++) {
                s[nt][half*2]   = __expf(s[nt][half*2]   - newm);
                s[nt][half*2+1] = __expf(s[nt][half*2+1] - newm);
                rs += s[nt][half*2] + s[nt][half*2+1];
            }
            rs += __shfl_xor_sync(0xffffffffu, rs, 1);
            rs += __shfl_xor_sync(0xffffffffu, rs, 2);
            li[half] = li[half] * corr + rs;
            mi[half] = newm;
            #pragma unroll
            for (int nt = 0; nt < 8; nt++) {
                accO[nt][half*2]   *= corr;
                accO[nt][half*2+1] *= corr;
            }
        }

        __syncthreads();   // all warps done reading K fragments from KP
        // store P (tf32) into KP: row = q row, col = key
        #pragma unroll
        for (int nt = 0; nt < 8; nt++) {
            const int c0 = nt*8 + tig*2;
            KP[m0 + gid    ][c0    ] = f2tf(s[nt][0]);
            KP[m0 + gid    ][c0 + 1] = f2tf(s[nt][1]);
            KP[m0 + gid + 8][c0    ] = f2tf(s[nt][2]);
            KP[m0 + gid + 8][c0 + 1] = f2tf(s[nt][3]);
        }
        __syncthreads();

        // O += P @ V  (k = key dim, nt = dh columns)
        #pragma unroll
        for (int ks = 0; ks < 8; ks++) {
            const int kb8 = ks * 8;
            uint32_t af[4];
            af[0] = KP[m0 + gid    ][kb8 + tig];
            af[1] = KP[m0 + gid + 8][kb8 + tig];
            af[2] = KP[m0 + gid    ][kb8 + tig + 4];
            af[3] = KP[m0 + gid + 8][kb8 + tig + 4];
            #pragma unroll
            for (int nt = 0; nt < 8; nt++) {
                uint32_t b0 = Vs[kb8 + tig    ][nt*8 + gid];
                uint32_t b1 = Vs[kb8 + tig + 4][nt*8 + gid];
                mma_tf32(accO[nt], af, b0, b1);
            }
        }
    }

    // epilogue: normalize, write ctx (B,L,D)
    const float inv0 = 1.f / li[0];
    const float inv1 = 1.f / li[1];
    const int r0 = qt*64 + m0 + gid;
    const int r1 = r0 + 8;
    #pragma unroll
    for (int nt = 0; nt < 8; nt++) {
        const int c = nt*8 + tig*2;
        float2 v0 = make_float2(accO[nt][0]*inv0, accO[nt][1]*inv0);
        float2 v1 = make_float2(accO[nt][2]*inv1, accO[nt][3]*inv1);
        *(float2*)&g_ctx[((size_t)(b*LL + r0)) * DD + h*DH + c] = v0;
        *(float2*)&g_ctx[((size_t)(b*LL + r1)) * DD + h*DH + c] = v1;
    }
}

// ---------------------------------------------------------------------------
extern "C" void kernel_launch(void* const* d_in, const int* in_sizes, int n_in,
                              void* d_out, int out_size)
{
    const float* x  = (const float*)d_in[0];
    const int* mask = (const int*)d_in[1];
    const float* wq = (const float*)d_in[2];
    const float* bq = (const float*)d_in[3];
    const float* wk = (const float*)d_in[4];
    const float* bk = (const float*)d_in[5];
    const float* wv = (const float*)d_in[6];
    const float* bv = (const float*)d_in[7];
    const float* wo = (const float*)d_in[8];
    const float* bo = (const float*)d_in[9];
    float* out = (float*)d_out;

    dim3 gg(DD/128, MM/128);   // 8 x 64 blocks
    gemm_tf32<<<gg, 256>>>(x, wq, bq, nullptr, 0);
    gemm_tf32<<<gg, 256>>>(x, wk, bk, nullptr, 1);
    gemm_tf32<<<gg, 256>>>(x, wv, bv, nullptr, 2);

    dim3 ga(LL/64, HH, BB);    // 32 x 16 x 4 blocks
    attn_tf32<<<ga, 128>>>(mask);

    gemm_tf32<<<gg, 256>>>(nullptr, wo, bo, out, 3);
}

// round 4
// speedup vs baseline: 3.1813x; 1.1795x over previous
#include <cuda_runtime.h>
#include <math.h>
#include <stdint.h>

#define BB   4
#define HH   16
#define LL   2048
#define DD   1024
#define DH   64
#define MM   (BB*LL)   // 8192 tokens

// Scratch (device globals: allocation-free, graph-capturable)
__device__ float g_q[(size_t)BB*HH*LL*DH];    // (B,H,L,dh) tf32 bits, pre-scaled by 0.125
__device__ float g_k[(size_t)BB*HH*LL*DH];    // tf32 bits
__device__ float g_v[(size_t)BB*HH*LL*DH];    // tf32 bits
__device__ float g_ctx[(size_t)MM*DD];        // (B,L,D) tf32 bits
__device__ float g_xt[(size_t)MM*DD];         // x converted to tf32 bits
__device__ float g_wt[(size_t)4*DD*DD];       // wq,wk,wv,wo converted to tf32 bits

__device__ __forceinline__ uint32_t f2tf(float f) {
    uint32_t u;
    asm("cvt.rna.tf32.f32 %0, %1;" : "=r"(u) : "f"(f));
    return u;
}

__device__ __forceinline__ void mma_tf32(float c[4], const uint32_t a[4],
                                         uint32_t b0, uint32_t b1) {
    asm volatile(
        "mma.sync.aligned.m16n8k8.row.col.f32.tf32.tf32.f32 "
        "{%0,%1,%2,%3}, {%4,%5,%6,%7}, {%8,%9}, {%0,%1,%2,%3};"
        : "+f"(c[0]), "+f"(c[1]), "+f"(c[2]), "+f"(c[3])
        : "r"(a[0]), "r"(a[1]), "r"(a[2]), "r"(a[3]), "r"(b0), "r"(b1));
}

__device__ __forceinline__ void cp16(uint32_t saddr, const void* gptr) {
    asm volatile("cp.async.cg.shared.global [%0], [%1], 16;"
                 :: "r"(saddr), "l"(gptr));
}
#define CP_COMMIT() asm volatile("cp.async.commit_group;")
#define CP_WAIT1()  asm volatile("cp.async.wait_group 1;")

// ---------------------------------------------------------------------------
// Pre-convert x and weights to tf32 bit patterns (stored as float).
// ---------------------------------------------------------------------------
__global__ void __launch_bounds__(256) cvt_kernel(
    const float* __restrict__ x,
    const float* __restrict__ wq, const float* __restrict__ wk,
    const float* __restrict__ wv, const float* __restrict__ wo)
{
    const size_t NX = (size_t)MM * DD / 4;
    const size_t NW = (size_t)DD * DD / 4;
    size_t i = (size_t)blockIdx.x * blockDim.x + threadIdx.x;
    if (i >= NX + 4 * NW) return;
    const float* src;
    float* dst;
    size_t off;
    if (i < NX) { src = x; dst = g_xt; off = i; }
    else {
        size_t j = i - NX;
        int w = (int)(j / NW);
        off = j % NW;
        src = (w == 0) ? wq : (w == 1) ? wk : (w == 2) ? wv : wo;
        dst = g_wt + (size_t)w * DD * DD;
    }
    float4 v = ((const float4*)src)[off];
    uint4 u;
    u.x = f2tf(v.x); u.y = f2tf(v.y); u.z = f2tf(v.z); u.w = f2tf(v.w);
    ((uint4*)dst)[off] = u;
}

// ---------------------------------------------------------------------------
// tf32 tensor-core GEMM with cp.async double buffering.
// out[m,n] = sum_k A[m,k]*W[n,k] + bias[n]
// mode 0/1/2: A=g_xt,  out=g_q/g_k/g_v (B,H,L,dh) remap, tf32-converted store
//             (mode 0 additionally scales by 0.125)
// mode 3    : A=g_ctx, out=Oext plain fp32 (M,N)
// Tile 128x128, BK=16, 256 threads (8 warps as 2x4; each warp 64x32).
// ---------------------------------------------------------------------------
__global__ void __launch_bounds__(256) gemm_tf32(
    const float* __restrict__ bias,
    float* __restrict__ Oext,
    int mode)
{
    const float* A = (mode == 3) ? g_ctx : g_xt;
    const float* W = g_wt + (size_t)mode * DD * DD;
    float* out = (mode == 0) ? g_q : (mode == 1) ? g_k : (mode == 2) ? g_v : Oext;

    __shared__ uint32_t As[2][128][20];   // [buf][m][k] pad 4
    __shared__ uint32_t Ws[2][128][20];   // [buf][n][k] pad 4

    const int tid  = threadIdx.x;
    const int wid  = tid >> 5;
    const int lane = tid & 31;
    const int gid  = lane >> 2;
    const int tig  = lane & 3;
    const int warp_m = (wid & 1) * 64;
    const int warp_n = (wid >> 1) * 32;
    const int bm = blockIdx.y * 128;
    const int bn = blockIdx.x * 128;

    const int lrow = tid >> 1;          // 0..127
    const int lc   = (tid & 1) * 8;     // 0 or 8

    const float* Arow = A + (size_t)(bm + lrow) * DD;
    const float* Wrow = W + (size_t)(bn + lrow) * DD;
    const uint32_t As_base = (uint32_t)__cvta_generic_to_shared(&As[0][0][0]);
    const uint32_t Ws_base = (uint32_t)__cvta_generic_to_shared(&Ws[0][0][0]);

    float acc[4][4][4];
    #pragma unroll
    for (int mt = 0; mt < 4; mt++)
        #pragma unroll
        for (int nt = 0; nt < 4; nt++)
            #pragma unroll
            for (int r = 0; r < 4; r++) acc[mt][nt][r] = 0.f;

    // prefetch k0=0 into buf 0
    {
        uint32_t da = As_base + ((0*128 + lrow)*20 + lc) * 4;
        uint32_t dw = Ws_base + ((0*128 + lrow)*20 + lc) * 4;
        cp16(da,      Arow + lc);
        cp16(da + 16, Arow + lc + 4);
        cp16(dw,      Wrow + lc);
        cp16(dw + 16, Wrow + lc + 4);
    }
    CP_COMMIT();

    int buf = 0;
    for (int k0 = 0; k0 < DD; k0 += 16) {
        if (k0 + 16 < DD) {
            const int nb = buf ^ 1;
            uint32_t da = As_base + ((nb*128 + lrow)*20 + lc) * 4;
            uint32_t dw = Ws_base + ((nb*128 + lrow)*20 + lc) * 4;
            cp16(da,      Arow + k0 + 16 + lc);
            cp16(da + 16, Arow + k0 + 16 + lc + 4);
            cp16(dw,      Wrow + k0 + 16 + lc);
            cp16(dw + 16, Wrow + k0 + 16 + lc + 4);
        }
        CP_COMMIT();
        CP_WAIT1();
        __syncthreads();

        #pragma unroll
        for (int ks = 0; ks < 2; ks++) {
            const int kb = ks * 8;
            uint32_t bf[4][2];
            #pragma unroll
            for (int nt = 0; nt < 4; nt++) {
                const int n = warp_n + nt*8 + gid;
                bf[nt][0] = Ws[buf][n][kb + tig];
                bf[nt][1] = Ws[buf][n][kb + tig + 4];
            }
            #pragma unroll
            for (int mt = 0; mt < 4; mt++) {
                const int m = warp_m + mt*16;
                uint32_t af[4];
                af[0] = As[buf][m + gid    ][kb + tig];
                af[1] = As[buf][m + gid + 8][kb + tig];
                af[2] = As[buf][m + gid    ][kb + tig + 4];
                af[3] = As[buf][m + gid + 8][kb + tig + 4];
                #pragma unroll
                for (int nt = 0; nt < 4; nt++)
                    mma_tf32(acc[mt][nt], af, bf[nt][0], bf[nt][1]);
            }
        }
        __syncthreads();   // done reading buf; next iter may overwrite it
        buf ^= 1;
    }

    // epilogue
    const float sc = (mode == 0) ? 0.125f : 1.f;
    #pragma unroll
    for (int mt = 0; mt < 4; mt++) {
        #pragma unroll
        for (int nt = 0; nt < 4; nt++) {
            const int col = bn + warp_n + nt*8 + tig*2;
            const float b0 = bias[col], b1 = bias[col + 1];
            #pragma unroll
            for (int half = 0; half < 2; half++) {
                const int m = bm + warp_m + mt*16 + gid + half*8;
                float vx = (acc[mt][nt][half*2 + 0] + b0) * sc;
                float vy = (acc[mt][nt][half*2 + 1] + b1) * sc;
                if (mode <= 2) {
                    const int bb = m >> 11;
                    const int ll = m & (LL - 1);
                    const int h  = col >> 6;
                    const int c  = col & (DH - 1);
                    uint2 u = make_uint2(f2tf(vx), f2tf(vy));
                    *(uint2*)&out[(((size_t)(bb*HH + h) * LL) + ll) * DH + c] = u;
                } else {
                    *(float2*)&out[(size_t)m * DD + col] = make_float2(vx, vy);
                }
            }
        }
    }
}

// ---------------------------------------------------------------------------
// tf32 flash attention: block = one (b,h,128-query tile), 256 threads
// (8 warps, each owns 16 q rows). 32 key tiles of 64. Q pre-scaled by 0.125.
// cp.async loads; V+mask prefetched one iteration ahead (double buffer).
// P stores vectorized (STS.64). P reuses the K buffer (rows 0..127).
// Dynamic smem: Qs 128x68 + KP 128x68 + Vs 2x64x72 + msk 2x64 = 107008 B.
// ---------------------------------------------------------------------------
#define ATTN_SMEM_WORDS (128*68 + 128*68 + 2*64*72 + 2*64)
#define ATTN_SMEM_BYTES (ATTN_SMEM_WORDS*4)

__global__ void __launch_bounds__(256, 2) attn_tf32(const int* __restrict__ mask)
{
    extern __shared__ uint32_t smem[];
    uint32_t (*Qs)[68] = (uint32_t(*)[68])smem;                 // [q row][d]
    uint32_t (*KP)[68] = (uint32_t(*)[68])(smem + 128*68);      // K rows 0..63 -> P rows 0..127
    uint32_t (*Vs)[72] = (uint32_t(*)[72])(smem + 2*128*68);    // [2*64][d]
    int* msk = (int*)(smem + 2*128*68 + 2*64*72);               // [2][64]

    const int qt  = blockIdx.x;    // 0..15
    const int h   = blockIdx.y;
    const int b   = blockIdx.z;
    const int tid = threadIdx.x;
    const int wid = tid >> 5;      // 0..7
    const int lane = tid & 31;
    const int gid = lane >> 2;
    const int tig = lane & 3;
    const int m0  = wid * 16;

    const size_t headoff = ((size_t)(b*HH + h)) * LL * DH;
    const float* qb = g_q + headoff + (size_t)qt * 128 * DH;
    const float* kb = g_k + headoff;
    const float* vb = g_v + headoff;
    const int* mrow = mask + (size_t)b * LL;

    const uint32_t Qs_base = (uint32_t)__cvta_generic_to_shared(&Qs[0][0]);
    const uint32_t KP_base = (uint32_t)__cvta_generic_to_shared(&KP[0][0]);
    const uint32_t Vs_base = (uint32_t)__cvta_generic_to_shared(&Vs[0][0]);
    const uint32_t mk_base = (uint32_t)__cvta_generic_to_shared(&msk[0]);

    // prefetch: Q (128x64), K(0), V(0)->buf0, msk(0)->buf0; one group
    #pragma unroll
    for (int rep = 0; rep < 8; rep++) {
        const int idx = rep*256 + tid;
        const int r   = idx >> 4;
        const int c4  = (idx & 15) * 4;
        cp16(Qs_base + (r*68 + c4)*4, qb + (size_t)r*DH + c4);
    }
    #pragma unroll
    for (int rep = 0; rep < 4; rep++) {
        const int idx = rep*256 + tid;
        const int r   = idx >> 4;
        const int c4  = (idx & 15) * 4;
        cp16(KP_base + (r*68 + c4)*4, kb + (size_t)r*DH + c4);
        cp16(Vs_base + (r*72 + c4)*4, vb + (size_t)r*DH + c4);
    }
    if (tid < 16) cp16(mk_base + tid*16, mrow + tid*4);
    CP_COMMIT();

    float accO[8][4];
    #pragma unroll
    for (int nt = 0; nt < 8; nt++)
        #pragma unroll
        for (int r = 0; r < 4; r++) accO[nt][r] = 0.f;
    float mi[2] = {-INFINITY, -INFINITY};
    float li[2] = {0.f, 0.f};

    for (int kt = 0; kt < 32; kt++) {
        const int cur = kt & 1;

        if (kt > 0) {
            __syncthreads();   // prev iter's PV reads of KP (P) complete
            // K(kt) into KP rows 0..63
            const float* kbt = kb + (size_t)kt * 64 * DH;
            #pragma unroll
            for (int rep = 0; rep < 4; rep++) {
                const int idx = rep*256 + tid;
                const int r   = idx >> 4;
                const int c4  = (idx & 15) * 4;
                cp16(KP_base + (r*68 + c4)*4, kbt + (size_t)r*DH + c4);
            }
            CP_COMMIT();
        }
        // prefetch V(kt+1) + msk(kt+1) into other buffer
        if (kt + 1 < 32) {
            const int nb = (kt + 1) & 1;
            const float* vbt = vb + (size_t)(kt + 1) * 64 * DH;
            #pragma unroll
            for (int rep = 0; rep < 4; rep++) {
                const int idx = rep*256 + tid;
                const int r   = idx >> 4;
                const int c4  = (idx & 15) * 4;
                cp16(Vs_base + ((nb*64 + r)*72 + c4)*4, vbt + (size_t)r*DH + c4);
            }
            if (tid < 16) cp16(mk_base + (nb*64 + tid*4)*4, mrow + (kt+1)*64 + tid*4);
        }
        CP_COMMIT();
        CP_WAIT1();           // K(kt), V(kt), msk(kt) ready; V(kt+1) in flight
        __syncthreads();

        // S = Q K^T (Q pre-scaled by 0.125)
        float s[8][4];
        #pragma unroll
        for (int nt = 0; nt < 8; nt++)
            #pragma unroll
            for (int r = 0; r < 4; r++) s[nt][r] = 0.f;

        #pragma unroll
        for (int ks = 0; ks < 8; ks++) {
            const int kb8 = ks * 8;
            uint32_t af[4];
            af[0] = Qs[m0 + gid    ][kb8 + tig];
            af[1] = Qs[m0 + gid + 8][kb8 + tig];
            af[2] = Qs[m0 + gid    ][kb8 + tig + 4];
            af[3] = Qs[m0 + gid + 8][kb8 + tig + 4];
            #pragma unroll
            for (int nt = 0; nt < 8; nt++) {
                uint32_t b0 = KP[nt*8 + gid][kb8 + tig];
                uint32_t b1 = KP[nt*8 + gid][kb8 + tig + 4];
                mma_tf32(s[nt], af, b0, b1);
            }
        }

        // mask (exact -1e9 like reference; scale already folded into Q)
        #pragma unroll
        for (int nt = 0; nt < 8; nt++) {
            const int c0 = nt*8 + tig*2;
            const int mm0 = msk[cur*64 + c0], mm1 = msk[cur*64 + c0 + 1];
            if (mm0) { s[nt][0] = -1e9f; s[nt][2] = -1e9f; }
            if (mm1) { s[nt][1] = -1e9f; s[nt][3] = -1e9f; }
        }

        // online softmax per row half (rows gid and gid+8)
        #pragma unroll
        for (int half = 0; half < 2; half++) {
            float rm = -INFINITY;
            #pragma unroll
            for (int nt = 0; nt < 8; nt++)
                rm = fmaxf(rm, fmaxf(s[nt][half*2], s[nt][half*2+1]));
            rm = fmaxf(rm, __shfl_xor_sync(0xffffffffu, rm, 1));
            rm = fmaxf(rm, __shfl_xor_sync(0xffffffffu, rm, 2));
            const float newm = fmaxf(mi[half], rm);
            const float corr = __expf(mi[half] - newm);
            float rs = 0.f;
            #pragma unroll
            for (int nt = 0; nt < 8; nt++) {
                s[nt][half*2]   = __expf(s[nt][half*2]   - newm);
                s[nt][half*2+1] = __expf(s[nt][half*2+1] - newm);
                rs += s[nt][half*2] + s[nt][half*2+1];
            }
            rs += __shfl_xor_sync(0xffffffffu, rs, 1);
            rs += __shfl_xor_sync(0xffffffffu, rs, 2);
            li[half] = li[half] * corr + rs;
            mi[half] = newm;
            #pragma unroll
            for (int nt = 0; nt < 8; nt++) {
                accO[nt][half*2]   *= corr;
                accO[nt][half*2+1] *= corr;
            }
        }

        __syncthreads();   // all warps done reading K fragments from KP
        // store P (tf32) into KP rows 0..127: row = q row, col = key
        #pragma unroll
        for (int nt = 0; nt < 8; nt++) {
            const int c0 = nt*8 + tig*2;
            *(uint2*)&KP[m0 + gid    ][c0] = make_uint2(f2tf(s[nt][0]), f2tf(s[nt][1]));
            *(uint2*)&KP[m0 + gid + 8][c0] = make_uint2(f2tf(s[nt][2]), f2tf(s[nt][3]));
        }
        __syncthreads();

        // O += P @ V
        #pragma unroll
        for (int ks = 0; ks < 8; ks++) {
            const int kb8 = ks * 8;
            uint32_t af[4];
            af[0] = KP[m0 + gid    ][kb8 + tig];
            af[1] = KP[m0 + gid + 8][kb8 + tig];
            af[2] = KP[m0 + gid    ][kb8 + tig + 4];
            af[3] = KP[m0 + gid + 8][kb8 + tig + 4];
            #pragma unroll
            for (int nt = 0; nt < 8; nt++) {
                uint32_t b0 = Vs[cur*64 + kb8 + tig    ][nt*8 + gid];
                uint32_t b1 = Vs[cur*64 + kb8 + tig + 4][nt*8 + gid];
                mma_tf32(accO[nt], af, b0, b1);
            }
        }
    }

    // epilogue: normalize, tf32-convert, write ctx (B,L,D)
    const float inv0 = 1.f / li[0];
    const float inv1 = 1.f / li[1];
    const int r0 = qt*128 + m0 + gid;
    const int r1 = r0 + 8;
    #pragma unroll
    for (int nt = 0; nt < 8; nt++) {
        const int c = h*DH + nt*8 + tig*2;
        uint2 u0 = make_uint2(f2tf(accO[nt][0]*inv0), f2tf(accO[nt][1]*inv0));
        uint2 u1 = make_uint2(f2tf(accO[nt][2]*inv1), f2tf(accO[nt][3]*inv1));
        *(uint2*)&g_ctx[((size_t)(b*LL + r0)) * DD + c] = u0;
        *(uint2*)&g_ctx[((size_t)(b*LL + r1)) * DD + c] = u1;
    }
}

// ---------------------------------------------------------------------------
extern "C" void kernel_launch(void* const* d_in, const int* in_sizes, int n_in,
                              void* d_out, int out_size)
{
    const float* x  = (const float*)d_in[0];
    const int* mask = (const int*)d_in[1];
    const float* wq = (const float*)d_in[2];
    const float* bq = (const float*)d_in[3];
    const float* wk = (const float*)d_in[4];
    const float* bk = (const float*)d_in[5];
    const float* wv = (const float*)d_in[6];
    const float* bv = (const float*)d_in[7];
    const float* wo = (const float*)d_in[8];
    const float* bo = (const float*)d_in[9];
    float* out = (float*)d_out;

    cudaFuncSetAttribute(attn_tf32, cudaFuncAttributeMaxDynamicSharedMemorySize,
                         ATTN_SMEM_BYTES);

    const int ncvt = (MM*DD/4 + 4*DD*DD/4 + 255) / 256;
    cvt_kernel<<<ncvt, 256>>>(x, wq, wk, wv, wo);

    dim3 gg(DD/128, MM/128);   // 8 x 64 blocks
    gemm_tf32<<<gg, 256>>>(bq, nullptr, 0);
    gemm_tf32<<<gg, 256>>>(bk, nullptr, 1);
    gemm_tf32<<<gg, 256>>>(bv, nullptr, 2);

    dim3 ga(LL/128, HH, BB);   // 16 x 16 x 4 blocks
    attn_tf32<<<ga, 256, ATTN_SMEM_BYTES>>>(mask);

    gemm_tf32<<<gg, 256>>>(bo, out, 3);
}

// round 5
// speedup vs baseline: 5.5023x; 1.7296x over previous
#include <cuda_runtime.h>
#include <cuda_fp16.h>
#include <math.h>
#include <stdint.h>

#define BB   4
#define HH   16
#define LL   2048
#define DD   1024
#define DH   64
#define MM   (BB*LL)   // 8192 tokens

// Scratch (device globals: allocation-free, graph-capturable). All fp16.
__device__ __half g_q[(size_t)BB*HH*LL*DH];    // (B,H,L,dh), pre-scaled by 0.125
__device__ __half g_k[(size_t)BB*HH*LL*DH];    // (B,H,L,dh)
__device__ __half g_v[(size_t)BB*HH*DH*LL];    // (B,H,dh,L)  TRANSPOSED
__device__ __half g_ctx[(size_t)MM*DD];        // (B,L,D)
__device__ __half g_xt[(size_t)MM*DD];         // x in fp16
__device__ __half g_wt[(size_t)4*DD*DD];       // wq,wk,wv,wo in fp16

__device__ __forceinline__ void mma_f16(float c[4], const uint32_t a[4],
                                        uint32_t b0, uint32_t b1) {
    asm volatile(
        "mma.sync.aligned.m16n8k16.row.col.f32.f16.f16.f32 "
        "{%0,%1,%2,%3}, {%4,%5,%6,%7}, {%8,%9}, {%0,%1,%2,%3};"
        : "+f"(c[0]), "+f"(c[1]), "+f"(c[2]), "+f"(c[3])
        : "r"(a[0]), "r"(a[1]), "r"(a[2]), "r"(a[3]), "r"(b0), "r"(b1));
}

__device__ __forceinline__ void cp16(uint32_t saddr, const void* gptr) {
    asm volatile("cp.async.cg.shared.global [%0], [%1], 16;"
                 :: "r"(saddr), "l"(gptr));
}
#define CP_COMMIT() asm volatile("cp.async.commit_group;")
#define CP_WAIT1()  asm volatile("cp.async.wait_group 1;")
#define CP_WAIT2()  asm volatile("cp.async.wait_group 2;")

__device__ __forceinline__ uint32_t pack2(float a, float b) {
    __half2 h = __floats2half2_rn(a, b);
    return *reinterpret_cast<uint32_t*>(&h);
}

// ---------------------------------------------------------------------------
// Convert x and the 4 weights to fp16.
// ---------------------------------------------------------------------------
__global__ void __launch_bounds__(256) cvt_kernel(
    const float* __restrict__ x,
    const float* __restrict__ wq, const float* __restrict__ wk,
    const float* __restrict__ wv, const float* __restrict__ wo)
{
    const size_t NX = (size_t)MM * DD / 4;
    const size_t NW = (size_t)DD * DD / 4;
    size_t i = (size_t)blockIdx.x * blockDim.x + threadIdx.x;
    if (i >= NX + 4 * NW) return;
    const float* src;
    __half* dst;
    size_t off;
    if (i < NX) { src = x; dst = g_xt; off = i; }
    else {
        size_t j = i - NX;
        int w = (int)(j / NW);
        off = j % NW;
        src = (w == 0) ? wq : (w == 1) ? wk : (w == 2) ? wv : wo;
        dst = g_wt + (size_t)w * DD * DD;
    }
    float4 v = ((const float4*)src)[off];
    ((__half2*)dst)[off*2]   = __floats2half2_rn(v.x, v.y);
    ((__half2*)dst)[off*2+1] = __floats2half2_rn(v.z, v.w);
}

// ---------------------------------------------------------------------------
// fp16 tensor-core GEMM, 4-stage cp.async pipeline, 1 barrier/iter.
// out[m,n] = sum_k A[m,k]*W[n,k] + bias[n]
// Tile 128x128, BK=32 halfs (2 k16-steps), 256 threads (8 warps, 64x32 each).
// mode 0: out=g_q half, scaled 0.125  | mode 1: out=g_k half
// mode 2: out=g_v half TRANSPOSED     | mode 3: A=g_ctx, out fp32 (M,N)
// smem row: 16 words (32 halfs) pad to 20.
// ---------------------------------------------------------------------------
#define GST 4
#define GEMM_SMEM (GST*2*128*20*4)

__global__ void __launch_bounds__(256, 2) gemm_f16(
    const float* __restrict__ bias,
    float* __restrict__ Oext,
    int mode)
{
    const __half* A = (mode == 3) ? g_ctx : g_xt;
    const __half* W = g_wt + (size_t)mode * DD * DD;

    extern __shared__ uint32_t sm[];   // [stage][2][128][20]

    const int tid  = threadIdx.x;
    const int wid  = tid >> 5;
    const int lane = tid & 31;
    const int gid  = lane >> 2;
    const int tig  = lane & 3;
    const int warp_m = (wid & 1) * 64;
    const int warp_n = (wid >> 1) * 32;
    const int bm = blockIdx.y * 128;
    const int bn = blockIdx.x * 128;

    const int mat = tid >> 7;      // 0 = A, 1 = W
    const int row = tid & 127;
    const __half* grow = mat ? (W + (size_t)(bn + row) * DD)
                             : (A + (size_t)(bm + row) * DD);
    const uint32_t smb = (uint32_t)__cvta_generic_to_shared(sm);
    const uint32_t mydst = smb + (uint32_t)(mat*128 + row) * 20 * 4;

    float acc[4][4][4];
    #pragma unroll
    for (int mt = 0; mt < 4; mt++)
        #pragma unroll
        for (int nt = 0; nt < 4; nt++)
            #pragma unroll
            for (int r = 0; r < 4; r++) acc[mt][nt][r] = 0.f;

    // issue stage it (BK=32 halfs = 64B per row)
    #define G_ISSUE(it) do { \
        uint32_t d = mydst + (uint32_t)((it) & 3) * (2*128*20*4); \
        const __half* s_ = grow + (it)*32; \
        cp16(d,      s_);      cp16(d + 16, s_ + 8); \
        cp16(d + 32, s_ + 16); cp16(d + 48, s_ + 24); \
    } while (0)

    G_ISSUE(0); CP_COMMIT();
    G_ISSUE(1); CP_COMMIT();

    for (int i = 0; i < 32; i++) {
        if (i + 2 < 32) G_ISSUE(i + 2);
        CP_COMMIT();
        CP_WAIT2();
        __syncthreads();

        uint32_t* Asb = sm + (size_t)(i & 3) * 2 * 128 * 20;
        uint32_t* Wsb = Asb + 128 * 20;

        #pragma unroll
        for (int ks = 0; ks < 2; ks++) {
            const int kb = ks * 8;
            uint32_t bf[4][2];
            #pragma unroll
            for (int nt = 0; nt < 4; nt++) {
                const int n = warp_n + nt*8 + gid;
                bf[nt][0] = Wsb[n*20 + kb + tig];
                bf[nt][1] = Wsb[n*20 + kb + tig + 4];
            }
            #pragma unroll
            for (int mt = 0; mt < 4; mt++) {
                const int m = warp_m + mt*16;
                uint32_t af[4];
                af[0] = Asb[(m + gid    )*20 + kb + tig];
                af[1] = Asb[(m + gid + 8)*20 + kb + tig];
                af[2] = Asb[(m + gid    )*20 + kb + tig + 4];
                af[3] = Asb[(m + gid + 8)*20 + kb + tig + 4];
                #pragma unroll
                for (int nt = 0; nt < 4; nt++)
                    mma_f16(acc[mt][nt], af, bf[nt][0], bf[nt][1]);
            }
        }
    }
    #undef G_ISSUE

    // epilogue
    const float sc = (mode == 0) ? 0.125f : 1.f;
    #pragma unroll
    for (int mt = 0; mt < 4; mt++) {
        #pragma unroll
        for (int nt = 0; nt < 4; nt++) {
            const int col = bn + warp_n + nt*8 + tig*2;
            const float b0 = bias[col], b1 = bias[col + 1];
            #pragma unroll
            for (int half_ = 0; half_ < 2; half_++) {
                const int m = bm + warp_m + mt*16 + gid + half_*8;
                float vx = (acc[mt][nt][half_*2 + 0] + b0) * sc;
                float vy = (acc[mt][nt][half_*2 + 1] + b1) * sc;
                if (mode == 3) {
                    *(float2*)&Oext[(size_t)m * DD + col] = make_float2(vx, vy);
                } else {
                    const int bb = m >> 11;
                    const int ll = m & (LL - 1);
                    const int h  = col >> 6;
                    const int c  = col & (DH - 1);
                    if (mode == 2) {   // V transposed: (B,H,dh,L)
                        const size_t base = ((size_t)(bb*HH + h)) * DH * LL;
                        g_v[base + (size_t)c    *LL + ll] = __float2half_rn(vx);
                        g_v[base + (size_t)(c+1)*LL + ll] = __float2half_rn(vy);
                    } else {
                        __half* dst = (mode == 0) ? g_q : g_k;
                        *(uint32_t*)&dst[(((size_t)(bb*HH + h)*LL) + ll)*DH + c] =
                            pack2(vx, vy);
                    }
                }
            }
        }
    }
}

// ---------------------------------------------------------------------------
// fp16 flash attention: 128-query tile, 256 threads (8 warps x 16 rows).
// 32 key tiles of 64. K/V/mask triple-buffered cp.async (prefetch at top),
// separate P buffer, 2 barriers/iter. V arrives pre-transposed [dh][L].
// smem words: Q 128*36, P 128*36, K 3*64*36, V 3*64*36, msk 3*64.
// ---------------------------------------------------------------------------
#define AQ_OFF 0
#define AP_OFF (128*36)
#define AK_OFF (2*128*36)
#define AV_OFF (AK_OFF + 3*64*36)
#define AM_OFF (AV_OFF + 3*64*36)
#define ATTN_SMEM ((AM_OFF + 3*64)*4)

__global__ void __launch_bounds__(256, 2) attn_f16(const int* __restrict__ mask)
{
    extern __shared__ uint32_t sm[];

    const int qt  = blockIdx.x;    // 0..15
    const int h   = blockIdx.y;
    const int b   = blockIdx.z;
    const int tid = threadIdx.x;
    const int wid = tid >> 5;
    const int lane = tid & 31;
    const int gid = lane >> 2;
    const int tig = lane & 3;
    const int m0  = wid * 16;

    const __half* qb = g_q + ((size_t)(b*HH + h))*LL*DH + (size_t)qt*128*DH;
    const __half* kb = g_k + ((size_t)(b*HH + h))*LL*DH;
    const __half* vb = g_v + ((size_t)(b*HH + h))*DH*LL;
    const int* mrow = mask + (size_t)b * LL;
    const uint32_t smb = (uint32_t)__cvta_generic_to_shared(sm);

    // issue K(kt), V(kt), msk(kt) into ring buffer kt%3
    #define A_ISSUE(kt_) do { \
        const int tb_ = (kt_) % 3; \
        const __half* ksrc_ = kb + (size_t)(kt_)*64*DH; \
        _Pragma("unroll") \
        for (int rep_ = 0; rep_ < 2; rep_++) { \
            int idx_ = rep_*256 + tid; \
            int r_ = idx_ >> 3, w_ = (idx_ & 7); \
            cp16(smb + (uint32_t)(AK_OFF + tb_*64*36 + r_*36 + w_*4)*4, \
                 ksrc_ + (size_t)r_*DH + w_*8); \
            cp16(smb + (uint32_t)(AV_OFF + tb_*64*36 + r_*36 + w_*4)*4, \
                 vb + (size_t)r_*LL + (kt_)*64 + w_*8); \
        } \
        if (tid < 16) cp16(smb + (uint32_t)(AM_OFF + tb_*64 + tid*4)*4, \
                           mrow + (kt_)*64 + tid*4); \
    } while (0)

    // prologue: Q (128 rows x 64 halfs) + tile 0, one group
    #pragma unroll
    for (int rep = 0; rep < 4; rep++) {
        int idx = rep*256 + tid;
        int r = idx >> 3, w = idx & 7;
        cp16(smb + (uint32_t)(AQ_OFF + r*36 + w*4)*4, qb + (size_t)r*DH + w*8);
    }
    A_ISSUE(0);
    CP_COMMIT();

    float accO[8][4];
    #pragma unroll
    for (int nt = 0; nt < 8; nt++)
        #pragma unroll
        for (int r = 0; r < 4; r++) accO[nt][r] = 0.f;
    float mi[2] = {-INFINITY, -INFINITY};
    float li[2] = {0.f, 0.f};

    for (int kt = 0; kt < 32; kt++) {
        const int tb = kt % 3;

        if (kt + 1 < 32) A_ISSUE(kt + 1);
        CP_COMMIT();
        CP_WAIT1();            // group kt done; kt+1 in flight
        __syncthreads();

        // S = Q K^T  (Q pre-scaled by 0.125)
        float s[8][4];
        #pragma unroll
        for (int nt = 0; nt < 8; nt++)
            #pragma unroll
            for (int r = 0; r < 4; r++) s[nt][r] = 0.f;

        uint32_t* Qw = sm + AQ_OFF;
        uint32_t* Kw = sm + AK_OFF + tb*64*36;
        #pragma unroll
        for (int ks = 0; ks < 4; ks++) {
            const int kb8 = ks * 8;
            uint32_t af[4];
            af[0] = Qw[(m0 + gid    )*36 + kb8 + tig];
            af[1] = Qw[(m0 + gid + 8)*36 + kb8 + tig];
            af[2] = Qw[(m0 + gid    )*36 + kb8 + tig + 4];
            af[3] = Qw[(m0 + gid + 8)*36 + kb8 + tig + 4];
            #pragma unroll
            for (int nt = 0; nt < 8; nt++) {
                uint32_t b0 = Kw[(nt*8 + gid)*36 + kb8 + tig];
                uint32_t b1 = Kw[(nt*8 + gid)*36 + kb8 + tig + 4];
                mma_f16(s[nt], af, b0, b1);
            }
        }

        // mask (exact -1e9, scale already in Q)
        const int* mk = (const int*)(sm + AM_OFF + tb*64);
        #pragma unroll
        for (int nt = 0; nt < 8; nt++) {
            const int c0 = nt*8 + tig*2;
            if (mk[c0])     { s[nt][0] = -1e9f; s[nt][2] = -1e9f; }
            if (mk[c0 + 1]) { s[nt][1] = -1e9f; s[nt][3] = -1e9f; }
        }

        // online softmax (rows gid, gid+8)
        #pragma unroll
        for (int half_ = 0; half_ < 2; half_++) {
            float rm = -INFINITY;
            #pragma unroll
            for (int nt = 0; nt < 8; nt++)
                rm = fmaxf(rm, fmaxf(s[nt][half_*2], s[nt][half_*2+1]));
            rm = fmaxf(rm, __shfl_xor_sync(0xffffffffu, rm, 1));
            rm = fmaxf(rm, __shfl_xor_sync(0xffffffffu, rm, 2));
            const float newm = fmaxf(mi[half_], rm);
            const float corr = __expf(mi[half_] - newm);
            float rs = 0.f;
            #pragma unroll
            for (int nt = 0; nt < 8; nt++) {
                s[nt][half_*2]   = __expf(s[nt][half_*2]   - newm);
                s[nt][half_*2+1] = __expf(s[nt][half_*2+1] - newm);
                rs += s[nt][half_*2] + s[nt][half_*2+1];
            }
            rs += __shfl_xor_sync(0xffffffffu, rs, 1);
            rs += __shfl_xor_sync(0xffffffffu, rs, 2);
            li[half_] = li[half_] * corr + rs;
            mi[half_] = newm;
            #pragma unroll
            for (int nt = 0; nt < 8; nt++) {
                accO[nt][half_*2]   *= corr;
                accO[nt][half_*2+1] *= corr;
            }
        }

        // store P (fp16 pairs; safe: all warps past top barrier)
        uint32_t* Pw = sm + AP_OFF;
        #pragma unroll
        for (int nt = 0; nt < 8; nt++) {
            const int wd = nt*4 + tig;
            Pw[(m0 + gid    )*36 + wd] = pack2(s[nt][0], s[nt][1]);
            Pw[(m0 + gid + 8)*36 + wd] = pack2(s[nt][2], s[nt][3]);
        }
        __syncthreads();

        // O += P @ V   (V transposed: rows = dh, words = key pairs)
        uint32_t* Vw = sm + AV_OFF + tb*64*36;
        #pragma unroll
        for (int ks = 0; ks < 4; ks++) {
            const int kb8 = ks * 8;
            uint32_t af[4];
            af[0] = Pw[(m0 + gid    )*36 + kb8 + tig];
            af[1] = Pw[(m0 + gid + 8)*36 + kb8 + tig];
            af[2] = Pw[(m0 + gid    )*36 + kb8 + tig + 4];
            af[3] = Pw[(m0 + gid + 8)*36 + kb8 + tig + 4];
            #pragma unroll
            for (int nt = 0; nt < 8; nt++) {
                uint32_t b0 = Vw[(nt*8 + gid)*36 + kb8 + tig];
                uint32_t b1 = Vw[(nt*8 + gid)*36 + kb8 + tig + 4];
                mma_f16(accO[nt], af, b0, b1);
            }
        }
    }
    #undef A_ISSUE

    // epilogue: normalize, fp16 pack, write ctx (B,L,D)
    const float inv0 = 1.f / li[0];
    const float inv1 = 1.f / li[1];
    const int r0 = qt*128 + m0 + gid;
    const int r1 = r0 + 8;
    #pragma unroll
    for (int nt = 0; nt < 8; nt++) {
        const int c = h*DH + nt*8 + tig*2;
        *(uint32_t*)&g_ctx[((size_t)(b*LL + r0))*DD + c] =
            pack2(accO[nt][0]*inv0, accO[nt][1]*inv0);
        *(uint32_t*)&g_ctx[((size_t)(b*LL + r1))*DD + c] =
            pack2(accO[nt][2]*inv1, accO[nt][3]*inv1);
    }
}

// ---------------------------------------------------------------------------
extern "C" void kernel_launch(void* const* d_in, const int* in_sizes, int n_in,
                              void* d_out, int out_size)
{
    const float* x  = (const float*)d_in[0];
    const int* mask = (const int*)d_in[1];
    const float* wq = (const float*)d_in[2];
    const float* bq = (const float*)d_in[3];
    const float* wk = (const float*)d_in[4];
    const float* bk = (const float*)d_in[5];
    const float* wv = (const float*)d_in[6];
    const float* bv = (const float*)d_in[7];
    const float* wo = (const float*)d_in[8];
    const float* bo = (const float*)d_in[9];
    float* out = (float*)d_out;

    cudaFuncSetAttribute(gemm_f16, cudaFuncAttributeMaxDynamicSharedMemorySize,
                         GEMM_SMEM);
    cudaFuncSetAttribute(attn_f16, cudaFuncAttributeMaxDynamicSharedMemorySize,
                         ATTN_SMEM);

    const int ncvt = (int)(((size_t)MM*DD/4 + (size_t)DD*DD + 255) / 256);
    cvt_kernel<<<ncvt, 256>>>(x, wq, wk, wv, wo);

    dim3 gg(DD/128, MM/128);   // 8 x 64 blocks
    gemm_f16<<<gg, 256, GEMM_SMEM>>>(bq, nullptr, 0);
    gemm_f16<<<gg, 256, GEMM_SMEM>>>(bk, nullptr, 1);
    gemm_f16<<<gg, 256, GEMM_SMEM>>>(bv, nullptr, 2);

    dim3 ga(LL/128, HH, BB);   // 16 x 16 x 4 blocks
    attn_f16<<<ga, 256, ATTN_SMEM>>>(mask);

    gemm_f16<<<gg, 256, GEMM_SMEM>>>(bo, out, 3);
}

// round 7
// speedup vs baseline: 5.9007x; 1.0724x over previous
#include <cuda_runtime.h>
#include <cuda_fp16.h>
#include <math.h>
#include <stdint.h>

#define BB   4
#define HH   16
#define LL   2048
#define DD   1024
#define DH   64
#define MM   (BB*LL)   // 8192 tokens

// Scratch (device globals: allocation-free, graph-capturable). All fp16.
__device__ __half g_q[(size_t)BB*HH*LL*DH];    // (B,H,L,dh), pre-scaled by 0.125
__device__ __half g_k[(size_t)BB*HH*LL*DH];    // (B,H,L,dh)
__device__ __half g_v[(size_t)BB*HH*DH*LL];    // (B,H,dh,L)  TRANSPOSED
__device__ __half g_ctx[(size_t)MM*DD];        // (B,L,D)
__device__ __half g_xt[(size_t)MM*DD];         // x in fp16
__device__ __half g_wt[(size_t)4*DD*DD];       // wq,wk,wv,wo in fp16

// ---------------- helpers ----------------
__device__ __forceinline__ void mma_f16(float c[4], const uint32_t a[4],
                                        uint32_t b0, uint32_t b1) {
    asm volatile(
        "mma.sync.aligned.m16n8k16.row.col.f32.f16.f16.f32 "
        "{%0,%1,%2,%3}, {%4,%5,%6,%7}, {%8,%9}, {%0,%1,%2,%3};"
        : "+f"(c[0]), "+f"(c[1]), "+f"(c[2]), "+f"(c[3])
        : "r"(a[0]), "r"(a[1]), "r"(a[2]), "r"(a[3]), "r"(b0), "r"(b1));
}
__device__ __forceinline__ void ldsm_x4(uint32_t r[4], uint32_t saddr) {
    asm volatile("ldmatrix.sync.aligned.m8n8.x4.shared.b16 {%0,%1,%2,%3}, [%4];"
                 : "=r"(r[0]), "=r"(r[1]), "=r"(r[2]), "=r"(r[3]) : "r"(saddr));
}
__device__ __forceinline__ void cp16(uint32_t saddr, const void* gptr) {
    asm volatile("cp.async.cg.shared.global [%0], [%1], 16;"
                 :: "r"(saddr), "l"(gptr));
}
#define CP_COMMIT() asm volatile("cp.async.commit_group;")
#define CP_WAIT1()  asm volatile("cp.async.wait_group 1;")
#define CP_WAIT2()  asm volatile("cp.async.wait_group 2;")

__device__ __forceinline__ uint32_t pack2(float a, float b) {
    __half2 h = __floats2half2_rn(a, b);
    return *reinterpret_cast<uint32_t*>(&h);
}
__device__ __forceinline__ uint32_t smem_u32(const void* p) {
    uint32_t a;
    asm("{ .reg .u64 t; cvta.to.shared.u64 t, %1; cvt.u32.u64 %0, t; }"
        : "=r"(a) : "l"(p));
    return a;
}

// ---------------------------------------------------------------------------
// Convert x and the 4 weights to fp16.
// ---------------------------------------------------------------------------
__global__ void __launch_bounds__(256) cvt_kernel(
    const float* __restrict__ x,
    const float* __restrict__ wq, const float* __restrict__ wk,
    const float* __restrict__ wv, const float* __restrict__ wo)
{
    const size_t NX = (size_t)MM * DD / 4;
    const size_t NW = (size_t)DD * DD / 4;
    size_t i = (size_t)blockIdx.x * blockDim.x + threadIdx.x;
    if (i >= NX + 4 * NW) return;
    const float* src;
    __half* dst;
    size_t off;
    if (i < NX) { src = x; dst = g_xt; off = i; }
    else {
        size_t j = i - NX;
        int w = (int)(j / NW);
        off = j % NW;
        src = (w == 0) ? wq : (w == 1) ? wk : (w == 2) ? wv : wo;
        dst = g_wt + (size_t)w * DD * DD;
    }
    float4 v = ((const float4*)src)[off];
    ((__half2*)dst)[off*2]   = __floats2half2_rn(v.x, v.y);
    ((__half2*)dst)[off*2+1] = __floats2half2_rn(v.z, v.w);
}

// ---------------------------------------------------------------------------
// fp16 GEMM: 128x128 tile, 128 threads (4 warps, each 64x64), BK=32,
// 4-stage cp.async ring, ldmatrix.x4 fragment loads, 1 barrier/iter.
// out[m,n] = sum_k A[m,k]*W[n,k] + bias[n]
// mode 0: g_q *0.125 | mode 1: g_k | mode 2: g_v TRANSPOSED | mode 3: fp32 out
// smem: 4 stages x (A 128x20w + B 128x20w) = 81920 B.
// ---------------------------------------------------------------------------
#define GROW 20
#define GSTW (2*128*GROW)           // words per stage
#define GEMM_SMEM (4*GSTW*4)

__global__ void __launch_bounds__(128, 2) gemm_f16(
    const float* __restrict__ bias,
    float* __restrict__ Oext,
    int mode)
{
    const __half* A = (mode == 3) ? g_ctx : g_xt;
    const __half* W = g_wt + (size_t)mode * DD * DD;

    extern __shared__ uint32_t sm[];

    const int tid  = threadIdx.x;
    const int wid  = tid >> 5;
    const int lane = tid & 31;
    const int gid  = lane >> 2;
    const int tig  = lane & 3;
    const int warp_m = (wid & 1) * 64;
    const int warp_n = (wid >> 1) * 64;
    const int bm = blockIdx.y * 128;
    const int bn = blockIdx.x * 128;

    const __half* arow = A + (size_t)(bm + tid) * DD;
    const __half* wrow = W + (size_t)(bn + tid) * DD;
    const uint32_t smb = smem_u32(sm);

    // ldmatrix per-lane addressing
    const int g  = lane >> 3;
    const int rr = lane & 7;
    const int a_row = warp_m + (g & 1) * 8 + rr;     // + mt*16
    const int a_kw  = (g >> 1) * 4;                  // + kb
    const int b_row = warp_n + (g >> 1) * 8 + rr;    // + j*16
    const int b_kw  = (g & 1) * 4;                   // + kb

    float acc[4][8][4];
    #pragma unroll
    for (int mt = 0; mt < 4; mt++)
        #pragma unroll
        for (int nt = 0; nt < 8; nt++)
            #pragma unroll
            for (int r = 0; r < 4; r++) acc[mt][nt][r] = 0.f;

    // thread tid loads A row tid and B row tid: 32 halfs = 4 cp16 each
    #define G_ISSUE(t_) do { \
        uint32_t base_ = smb + ((t_) & 3) * GSTW * 4; \
        uint32_t da_ = base_ + (uint32_t)tid * GROW * 4; \
        uint32_t db_ = da_ + 128 * GROW * 4; \
        const __half* ga_ = arow + (t_) * 32; \
        const __half* gb_ = wrow + (t_) * 32; \
        cp16(da_,      ga_);      cp16(da_ + 16, ga_ + 8); \
        cp16(da_ + 32, ga_ + 16); cp16(da_ + 48, ga_ + 24); \
        cp16(db_,      gb_);      cp16(db_ + 16, gb_ + 8); \
        cp16(db_ + 32, gb_ + 16); cp16(db_ + 48, gb_ + 24); \
    } while (0)

    G_ISSUE(0); CP_COMMIT();
    G_ISSUE(1); CP_COMMIT();

    for (int i = 0; i < 32; i++) {
        if (i + 2 < 32) G_ISSUE(i + 2);
        CP_COMMIT();
        CP_WAIT2();
        __syncthreads();

        const uint32_t Ab = smb + (i & 3) * GSTW * 4;
        const uint32_t Bb = Ab + 128 * GROW * 4;

        #pragma unroll
        for (int ks = 0; ks < 2; ks++) {
            const int kb = ks * 8;
            uint32_t af[4][4];
            #pragma unroll
            for (int mt = 0; mt < 4; mt++)
                ldsm_x4(af[mt], Ab + (uint32_t)((a_row + mt*16)*GROW + kb + a_kw)*4);
            #pragma unroll
            for (int j = 0; j < 4; j++) {
                uint32_t bf[4];
                ldsm_x4(bf, Bb + (uint32_t)((b_row + j*16)*GROW + kb + b_kw)*4);
                #pragma unroll
                for (int mt = 0; mt < 4; mt++) {
                    mma_f16(acc[mt][2*j],   af[mt], bf[0], bf[1]);
                    mma_f16(acc[mt][2*j+1], af[mt], bf[2], bf[3]);
                }
            }
        }
    }
    #undef G_ISSUE

    // epilogue
    const float sc = (mode == 0) ? 0.125f : 1.f;
    #pragma unroll
    for (int mt = 0; mt < 4; mt++) {
        #pragma unroll
        for (int nt = 0; nt < 8; nt++) {
            const int col = bn + warp_n + nt*8 + tig*2;
            const float b0 = bias[col], b1 = bias[col + 1];
            #pragma unroll
            for (int half_ = 0; half_ < 2; half_++) {
                const int m = bm + warp_m + mt*16 + gid + half_*8;
                float vx = (acc[mt][nt][half_*2 + 0] + b0) * sc;
                float vy = (acc[mt][nt][half_*2 + 1] + b1) * sc;
                if (mode == 3) {
                    *(float2*)&Oext[(size_t)m * DD + col] = make_float2(vx, vy);
                } else {
                    const int bb = m >> 11;
                    const int ll = m & (LL - 1);
                    const int h  = col >> 6;
                    const int c  = col & (DH - 1);
                    if (mode == 2) {   // V transposed: (B,H,dh,L)
                        const size_t base = ((size_t)(bb*HH + h)) * DH * LL;
                        g_v[base + (size_t)c    *LL + ll] = __float2half_rn(vx);
                        g_v[base + (size_t)(c+1)*LL + ll] = __float2half_rn(vy);
                    } else {
                        __half* dst = (mode == 0) ? g_q : g_k;
                        *(uint32_t*)&dst[(((size_t)(bb*HH + h)*LL) + ll)*DH + c] =
                            pack2(vx, vy);
                    }
                }
            }
        }
    }
}

// ---------------------------------------------------------------------------
// fp16 flash attention with ldmatrix fragment loads.
// 128-query tile, 256 threads (8 warps x 16 q rows). 32 key tiles of 64.
// K/V/mask triple-buffered cp.async, separate P buffer, 2 barriers/iter.
// V arrives pre-transposed [dh][L].
// ---------------------------------------------------------------------------
#define AQ_OFF 0
#define AP_OFF (128*36)
#define AK_OFF (2*128*36)
#define AV_OFF (AK_OFF + 3*64*36)
#define AM_OFF (AV_OFF + 3*64*36)
#define ATTN_SMEM ((AM_OFF + 3*64)*4)

__global__ void __launch_bounds__(256, 2) attn_f16(const int* __restrict__ mask)
{
    extern __shared__ uint32_t sm[];

    const int qt  = blockIdx.x;
    const int h   = blockIdx.y;
    const int b   = blockIdx.z;
    const int tid = threadIdx.x;
    const int wid = tid >> 5;
    const int lane = tid & 31;
    const int gid = lane >> 2;
    const int tig = lane & 3;
    const int m0  = wid * 16;

    const __half* qb = g_q + ((size_t)(b*HH + h))*LL*DH + (size_t)qt*128*DH;
    const __half* kb = g_k + ((size_t)(b*HH + h))*LL*DH;
    const __half* vb = g_v + ((size_t)(b*HH + h))*DH*LL;
    const int* mrow = mask + (size_t)b * LL;
    const uint32_t smb = smem_u32(sm);

    // ldmatrix per-lane addressing
    const int g  = lane >> 3;
    const int rr = lane & 7;
    const int a_row = (g & 1) * 8 + rr;   // A-type (Q, P): + m0
    const int a_kw  = (g >> 1) * 4;
    const int b_row = (g >> 1) * 8 + rr;  // B-type (K, V): + j*16
    const int b_kw  = (g & 1) * 4;

    #define A_ISSUE(kt_) do { \
        const int tb_ = (kt_) % 3; \
        const __half* ksrc_ = kb + (size_t)(kt_)*64*DH; \
        _Pragma("unroll") \
        for (int rep_ = 0; rep_ < 2; rep_++) { \
            int idx_ = rep_*256 + tid; \
            int r_ = idx_ >> 3, w_ = (idx_ & 7); \
            cp16(smb + (uint32_t)(AK_OFF + tb_*64*36 + r_*36 + w_*4)*4, \
                 ksrc_ + (size_t)r_*DH + w_*8); \
            cp16(smb + (uint32_t)(AV_OFF + tb_*64*36 + r_*36 + w_*4)*4, \
                 vb + (size_t)r_*LL + (kt_)*64 + w_*8); \
        } \
        if (tid < 16) cp16(smb + (uint32_t)(AM_OFF + tb_*64 + tid*4)*4, \
                           mrow + (kt_)*64 + tid*4); \
    } while (0)

    #pragma unroll
    for (int rep = 0; rep < 4; rep++) {
        int idx = rep*256 + tid;
        int r = idx >> 3, w = idx & 7;
        cp16(smb + (uint32_t)(AQ_OFF + r*36 + w*4)*4, qb + (size_t)r*DH + w*8);
    }
    A_ISSUE(0);
    CP_COMMIT();

    float accO[8][4];
    #pragma unroll
    for (int nt = 0; nt < 8; nt++)
        #pragma unroll
        for (int r = 0; r < 4; r++) accO[nt][r] = 0.f;
    float mi[2] = {-INFINITY, -INFINITY};
    float li[2] = {0.f, 0.f};

    for (int kt = 0; kt < 32; kt++) {
        const int tb = kt % 3;

        if (kt + 1 < 32) A_ISSUE(kt + 1);
        CP_COMMIT();
        CP_WAIT1();
        __syncthreads();

        // S = Q K^T  (Q pre-scaled by 0.125)
        float s[8][4];
        #pragma unroll
        for (int nt = 0; nt < 8; nt++)
            #pragma unroll
            for (int r = 0; r < 4; r++) s[nt][r] = 0.f;

        const uint32_t Qb = smb + (uint32_t)(AQ_OFF + (m0 + a_row)*36)*4;
        const uint32_t Kb = smb + (uint32_t)(AK_OFF + tb*64*36)*4;
        #pragma unroll
        for (int ks = 0; ks < 4; ks++) {
            const int kb8 = ks * 8;
            uint32_t af[4];
            ldsm_x4(af, Qb + (uint32_t)(kb8 + a_kw)*4);
            #pragma unroll
            for (int j = 0; j < 4; j++) {
                uint32_t bf[4];
                ldsm_x4(bf, Kb + (uint32_t)((j*16 + b_row)*36 + kb8 + b_kw)*4);
                mma_f16(s[2*j],   af, bf[0], bf[1]);
                mma_f16(s[2*j+1], af, bf[2], bf[3]);
            }
        }

        // mask (exact -1e9, scale already in Q)
        const int* mk = (const int*)(sm + AM_OFF + tb*64);
        #pragma unroll
        for (int nt = 0; nt < 8; nt++) {
            const int c0 = nt*8 + tig*2;
            if (mk[c0])     { s[nt][0] = -1e9f; s[nt][2] = -1e9f; }
            if (mk[c0 + 1]) { s[nt][1] = -1e9f; s[nt][3] = -1e9f; }
        }

        // online softmax (rows gid, gid+8)
        #pragma unroll
        for (int half_ = 0; half_ < 2; half_++) {
            float rm = -INFINITY;
            #pragma unroll
            for (int nt = 0; nt < 8; nt++)
                rm = fmaxf(rm, fmaxf(s[nt][half_*2], s[nt][half_*2+1]));
            rm = fmaxf(rm, __shfl_xor_sync(0xffffffffu, rm, 1));
            rm = fmaxf(rm, __shfl_xor_sync(0xffffffffu, rm, 2));
            const float newm = fmaxf(mi[half_], rm);
            const float corr = __expf(mi[half_] - newm);
            float rs = 0.f;
            #pragma unroll
            for (int nt = 0; nt < 8; nt++) {
                s[nt][half_*2]   = __expf(s[nt][half_*2]   - newm);
                s[nt][half_*2+1] = __expf(s[nt][half_*2+1] - newm);
                rs += s[nt][half_*2] + s[nt][half_*2+1];
            }
            rs += __shfl_xor_sync(0xffffffffu, rs, 1);
            rs += __shfl_xor_sync(0xffffffffu, rs, 2);
            li[half_] = li[half_] * corr + rs;
            mi[half_] = newm;
            #pragma unroll
            for (int nt = 0; nt < 8; nt++) {
                accO[nt][half_*2]   *= corr;
                accO[nt][half_*2+1] *= corr;
            }
        }

        // store P (fp16 pairs)
        uint32_t* Pw = sm + AP_OFF;
        #pragma unroll
        for (int nt = 0; nt < 8; nt++) {
            const int wd = nt*4 + tig;
            Pw[(m0 + gid    )*36 + wd] = pack2(s[nt][0], s[nt][1]);
            Pw[(m0 + gid + 8)*36 + wd] = pack2(s[nt][2], s[nt][3]);
        }
        __syncthreads();

        // O += P @ V   (V rows = dh, words = key pairs)
        const uint32_t Pb = smb + (uint32_t)(AP_OFF + (m0 + a_row)*36)*4;
        const uint32_t Vb = smb + (uint32_t)(AV_OFF + tb*64*36)*4;
        #pragma unroll
        for (int ks = 0; ks < 4; ks++) {
            const int kb8 = ks * 8;
            uint32_t af[4];
            ldsm_x4(af, Pb + (uint32_t)(kb8 + a_kw)*4);
            #pragma unroll
            for (int j = 0; j < 4; j++) {
                uint32_t bf[4];
                ldsm_x4(bf, Vb + (uint32_t)((j*16 + b_row)*36 + kb8 + b_kw)*4);
                mma_f16(accO[2*j],   af, bf[0], bf[1]);
                mma_f16(accO[2*j+1], af, bf[2], bf[3]);
            }
        }
    }
    #undef A_ISSUE

    // epilogue: normalize, fp16 pack, write ctx (B,L,D)
    const float inv0 = 1.f / li[0];
    const float inv1 = 1.f / li[1];
    const int r0 = qt*128 + m0 + gid;
    const int r1 = r0 + 8;
    #pragma unroll
    for (int nt = 0; nt < 8; nt++) {
        const int c = h*DH + nt*8 + tig*2;
        *(uint32_t*)&g_ctx[((size_t)(b*LL + r0))*DD + c] =
            pack2(accO[nt][0]*inv0, accO[nt][1]*inv0);
        *(uint32_t*)&g_ctx[((size_t)(b*LL + r1))*DD + c] =
            pack2(accO[nt][2]*inv1, accO[nt][3]*inv1);
    }
}

// ---------------------------------------------------------------------------
extern "C" void kernel_launch(void* const* d_in, const int* in_sizes, int n_in,
                              void* d_out, int out_size)
{
    const float* x  = (const float*)d_in[0];
    const int* mask = (const int*)d_in[1];
    const float* wq = (const float*)d_in[2];
    const float* bq = (const float*)d_in[3];
    const float* wk = (const float*)d_in[4];
    const float* bk = (const float*)d_in[5];
    const float* wv = (const float*)d_in[6];
    const float* bv = (const float*)d_in[7];
    const float* wo = (const float*)d_in[8];
    const float* bo = (const float*)d_in[9];
    float* out = (float*)d_out;

    cudaFuncSetAttribute(gemm_f16, cudaFuncAttributeMaxDynamicSharedMemorySize,
                         GEMM_SMEM);
    cudaFuncSetAttribute(attn_f16, cudaFuncAttributeMaxDynamicSharedMemorySize,
                         ATTN_SMEM);

    const int ncvt = (int)(((size_t)MM*DD/4 + (size_t)DD*DD + 255) / 256);
    cvt_kernel<<<ncvt, 256>>>(x, wq, wk, wv, wo);

    dim3 gg(DD/128, MM/128);   // 8 x 64 blocks
    gemm_f16<<<gg, 128, GEMM_SMEM>>>(bq, nullptr, 0);
    gemm_f16<<<gg, 128, GEMM_SMEM>>>(bk, nullptr, 1);
    gemm_f16<<<gg, 128, GEMM_SMEM>>>(bv, nullptr, 2);

    dim3 ga(LL/128, HH, BB);   // 16 x 16 x 4 blocks
    attn_f16<<<ga, 256, ATTN_SMEM>>>(mask);

    gemm_f16<<<gg, 128, GEMM_SMEM>>>(bo, out, 3);
}

// round 8
// speedup vs baseline: 6.1577x; 1.0436x over previous
#include <cuda_runtime.h>
#include <cuda_fp16.h>
#include <math.h>
#include <stdint.h>

#define BB   4
#define HH   16
#define LL   2048
#define DD   1024
#define DH   64
#define MM   (BB*LL)   // 8192 tokens

// Scratch (device globals: allocation-free, graph-capturable). All fp16.
__device__ __half g_q[(size_t)BB*HH*LL*DH];    // (B,H,L,dh), pre-scaled by 0.125
__device__ __half g_k[(size_t)BB*HH*LL*DH];    // (B,H,L,dh)
__device__ __half g_v[(size_t)BB*HH*DH*LL];    // (B,H,dh,L)  TRANSPOSED
__device__ __half g_ctx[(size_t)MM*DD];        // (B,L,D)
__device__ __half g_xt[(size_t)MM*DD];         // x in fp16
__device__ __half g_wt[(size_t)4*DD*DD];       // wq,wk,wv,wo in fp16 (contiguous!)

// ---------------- helpers ----------------
__device__ __forceinline__ void mma_f16(float c[4], const uint32_t a[4],
                                        uint32_t b0, uint32_t b1) {
    asm volatile(
        "mma.sync.aligned.m16n8k16.row.col.f32.f16.f16.f32 "
        "{%0,%1,%2,%3}, {%4,%5,%6,%7}, {%8,%9}, {%0,%1,%2,%3};"
        : "+f"(c[0]), "+f"(c[1]), "+f"(c[2]), "+f"(c[3])
        : "r"(a[0]), "r"(a[1]), "r"(a[2]), "r"(a[3]), "r"(b0), "r"(b1));
}
__device__ __forceinline__ void ldsm_x4(uint32_t r[4], uint32_t saddr) {
    asm volatile("ldmatrix.sync.aligned.m8n8.x4.shared.b16 {%0,%1,%2,%3}, [%4];"
                 : "=r"(r[0]), "=r"(r[1]), "=r"(r[2]), "=r"(r[3]) : "r"(saddr));
}
__device__ __forceinline__ void cp16(uint32_t saddr, const void* gptr) {
    asm volatile("cp.async.cg.shared.global [%0], [%1], 16;"
                 :: "r"(saddr), "l"(gptr));
}
#define CP_COMMIT() asm volatile("cp.async.commit_group;")
#define CP_WAIT1()  asm volatile("cp.async.wait_group 1;")
#define CP_WAIT2()  asm volatile("cp.async.wait_group 2;")

__device__ __forceinline__ uint32_t pack2(float a, float b) {
    __half2 h = __floats2half2_rn(a, b);
    return *reinterpret_cast<uint32_t*>(&h);
}
__device__ __forceinline__ uint32_t smem_u32(const void* p) {
    uint32_t a;
    asm("{ .reg .u64 t; cvta.to.shared.u64 t, %1; cvt.u32.u64 %0, t; }"
        : "=r"(a) : "l"(p));
    return a;
}

// ---------------------------------------------------------------------------
// Convert x and the 4 weights to fp16.
// ---------------------------------------------------------------------------
__global__ void __launch_bounds__(256) cvt_kernel(
    const float* __restrict__ x,
    const float* __restrict__ wq, const float* __restrict__ wk,
    const float* __restrict__ wv, const float* __restrict__ wo)
{
    const size_t NX = (size_t)MM * DD / 4;
    const size_t NW = (size_t)DD * DD / 4;
    size_t i = (size_t)blockIdx.x * blockDim.x + threadIdx.x;
    if (i >= NX + 4 * NW) return;
    const float* src;
    __half* dst;
    size_t off;
    if (i < NX) { src = x; dst = g_xt; off = i; }
    else {
        size_t j = i - NX;
        int w = (int)(j / NW);
        off = j % NW;
        src = (w == 0) ? wq : (w == 1) ? wk : (w == 2) ? wv : wo;
        dst = g_wt + (size_t)w * DD * DD;
    }
    float4 v = ((const float4*)src)[off];
    ((__half2*)dst)[off*2]   = __floats2half2_rn(v.x, v.y);
    ((__half2*)dst)[off*2+1] = __floats2half2_rn(v.z, v.w);
}

// ---------------------------------------------------------------------------
// fp16 GEMM: 128x128 tile, 256 threads (8 warps as 2x4, each 64x32 tile),
// BK=32, 4-stage cp.async ring, ldmatrix.x4 fragment loads, 1 barrier/iter.
// out[m,n] = sum_k A[m,k]*W[n,k] + bias[n]
// mode 0: MERGED QKV (N=3072): block's weight-col range selects q/k/v routing
//         (q scaled 0.125, v stored transposed (B,H,dh,L))
// mode 3: A=g_ctx, W=wo, plain fp32 out (M,N)
// smem: 4 stages x (A 128x20w + B 128x20w) = 81920 B -> 2 CTAs/SM.
// ---------------------------------------------------------------------------
#define GROW 20
#define GSTW (2*128*GROW)           // words per stage
#define GEMM_SMEM (4*GSTW*4)

__global__ void __launch_bounds__(256, 2) gemm_f16(
    const float* __restrict__ bq_, const float* __restrict__ bk_,
    const float* __restrict__ bv_, float* __restrict__ Oext,
    int mode)
{
    const __half* A = (mode == 3) ? g_ctx : g_xt;
    const __half* W = (mode == 3) ? (g_wt + (size_t)3*DD*DD) : g_wt;

    extern __shared__ uint32_t sm[];

    const int tid  = threadIdx.x;
    const int wid  = tid >> 5;
    const int lane = tid & 31;
    const int gid  = lane >> 2;
    const int tig  = lane & 3;
    const int warp_m = (wid & 1) * 64;
    const int warp_n = (wid >> 1) * 32;
    const int bm = blockIdx.y * 128;
    const int bn = blockIdx.x * 128;

    // loader: thread tid -> matrix (tid>>7), row (tid&127), 32 halfs
    const int lmat = tid >> 7;
    const int lrow = tid & 127;
    const __half* grow = lmat ? (W + (size_t)(bn + lrow) * DD)
                              : (A + (size_t)(bm + lrow) * DD);
    const uint32_t smb = smem_u32(sm);
    const uint32_t ldst = smb + (uint32_t)(lmat*128 + lrow) * GROW * 4;

    // ldmatrix per-lane addressing
    const int g  = lane >> 3;
    const int rr = lane & 7;
    const int a_row = warp_m + (g & 1) * 8 + rr;     // + mt*16
    const int a_kw  = (g >> 1) * 4;                  // + kb
    const int b_row = warp_n + (g >> 1) * 8 + rr;    // + j*16
    const int b_kw  = (g & 1) * 4;                   // + kb

    float acc[4][4][4];
    #pragma unroll
    for (int mt = 0; mt < 4; mt++)
        #pragma unroll
        for (int nt = 0; nt < 4; nt++)
            #pragma unroll
            for (int r = 0; r < 4; r++) acc[mt][nt][r] = 0.f;

    #define G_ISSUE(t_) do { \
        uint32_t d_ = ldst + ((t_) & 3) * GSTW * 4; \
        const __half* s_ = grow + (t_) * 32; \
        cp16(d_,      s_);      cp16(d_ + 16, s_ + 8); \
        cp16(d_ + 32, s_ + 16); cp16(d_ + 48, s_ + 24); \
    } while (0)

    G_ISSUE(0); CP_COMMIT();
    G_ISSUE(1); CP_COMMIT();

    for (int i = 0; i < 32; i++) {
        if (i + 2 < 32) G_ISSUE(i + 2);
        CP_COMMIT();
        CP_WAIT2();
        __syncthreads();

        const uint32_t Ab = smb + (i & 3) * GSTW * 4;
        const uint32_t Bb = Ab + 128 * GROW * 4;

        #pragma unroll
        for (int ks = 0; ks < 2; ks++) {
            const int kb = ks * 8;
            uint32_t af[4][4];
            #pragma unroll
            for (int mt = 0; mt < 4; mt++)
                ldsm_x4(af[mt], Ab + (uint32_t)((a_row + mt*16)*GROW + kb + a_kw)*4);
            #pragma unroll
            for (int j = 0; j < 2; j++) {
                uint32_t bf[4];
                ldsm_x4(bf, Bb + (uint32_t)((b_row + j*16)*GROW + kb + b_kw)*4);
                #pragma unroll
                for (int mt = 0; mt < 4; mt++) {
                    mma_f16(acc[mt][2*j],   af[mt], bf[0], bf[1]);
                    mma_f16(acc[mt][2*j+1], af[mt], bf[2], bf[3]);
                }
            }
        }
    }
    #undef G_ISSUE

    // epilogue
    // mode 0: which = bn>>10 selects q(0)/k(1)/v(2); local col = n & 1023
    const int which = (mode == 3) ? 3 : (bn >> 10);
    const float* bias = (which == 0) ? bq_ : (which == 1) ? bk_ : bv_;
    const float sc = (which == 0) ? 0.125f : 1.f;

    #pragma unroll
    for (int mt = 0; mt < 4; mt++) {
        #pragma unroll
        for (int nt = 0; nt < 4; nt++) {
            const int col = bn + warp_n + nt*8 + tig*2;   // global N col
            const int lc  = col & 1023;                    // local within matrix
            const float b0 = (mode == 3) ? bq_[lc] : bias[lc];
            const float b1 = (mode == 3) ? bq_[lc+1] : bias[lc+1];
            #pragma unroll
            for (int half_ = 0; half_ < 2; half_++) {
                const int m = bm + warp_m + mt*16 + gid + half_*8;
                float vx = (acc[mt][nt][half_*2 + 0] + b0) * sc;
                float vy = (acc[mt][nt][half_*2 + 1] + b1) * sc;
                if (mode == 3) {
                    *(float2*)&Oext[(size_t)m * DD + lc] = make_float2(vx, vy);
                } else {
                    const int bb = m >> 11;
                    const int ll = m & (LL - 1);
                    const int h  = lc >> 6;
                    const int c  = lc & (DH - 1);
                    if (which == 2) {   // V transposed: (B,H,dh,L)
                        const size_t base = ((size_t)(bb*HH + h)) * DH * LL;
                        g_v[base + (size_t)c    *LL + ll] = __float2half_rn(vx);
                        g_v[base + (size_t)(c+1)*LL + ll] = __float2half_rn(vy);
                    } else {
                        __half* dst = (which == 0) ? g_q : g_k;
                        *(uint32_t*)&dst[(((size_t)(bb*HH + h)*LL) + ll)*DH + c] =
                            pack2(vx, vy);
                    }
                }
            }
        }
    }
}

// ---------------------------------------------------------------------------
// fp16 flash attention with ldmatrix fragment loads (unchanged from R7).
// ---------------------------------------------------------------------------
#define AQ_OFF 0
#define AP_OFF (128*36)
#define AK_OFF (2*128*36)
#define AV_OFF (AK_OFF + 3*64*36)
#define AM_OFF (AV_OFF + 3*64*36)
#define ATTN_SMEM ((AM_OFF + 3*64)*4)

__global__ void __launch_bounds__(256, 2) attn_f16(const int* __restrict__ mask)
{
    extern __shared__ uint32_t sm[];

    const int qt  = blockIdx.x;
    const int h   = blockIdx.y;
    const int b   = blockIdx.z;
    const int tid = threadIdx.x;
    const int wid = tid >> 5;
    const int lane = tid & 31;
    const int gid = lane >> 2;
    const int tig = lane & 3;
    const int m0  = wid * 16;

    const __half* qb = g_q + ((size_t)(b*HH + h))*LL*DH + (size_t)qt*128*DH;
    const __half* kb = g_k + ((size_t)(b*HH + h))*LL*DH;
    const __half* vb = g_v + ((size_t)(b*HH + h))*DH*LL;
    const int* mrow = mask + (size_t)b * LL;
    const uint32_t smb = smem_u32(sm);

    const int g  = lane >> 3;
    const int rr = lane & 7;
    const int a_row = (g & 1) * 8 + rr;
    const int a_kw  = (g >> 1) * 4;
    const int b_row = (g >> 1) * 8 + rr;
    const int b_kw  = (g & 1) * 4;

    #define A_ISSUE(kt_) do { \
        const int tb_ = (kt_) % 3; \
        const __half* ksrc_ = kb + (size_t)(kt_)*64*DH; \
        _Pragma("unroll") \
        for (int rep_ = 0; rep_ < 2; rep_++) { \
            int idx_ = rep_*256 + tid; \
            int r_ = idx_ >> 3, w_ = (idx_ & 7); \
            cp16(smb + (uint32_t)(AK_OFF + tb_*64*36 + r_*36 + w_*4)*4, \
                 ksrc_ + (size_t)r_*DH + w_*8); \
            cp16(smb + (uint32_t)(AV_OFF + tb_*64*36 + r_*36 + w_*4)*4, \
                 vb + (size_t)r_*LL + (kt_)*64 + w_*8); \
        } \
        if (tid < 16) cp16(smb + (uint32_t)(AM_OFF + tb_*64 + tid*4)*4, \
                           mrow + (kt_)*64 + tid*4); \
    } while (0)

    #pragma unroll
    for (int rep = 0; rep < 4; rep++) {
        int idx = rep*256 + tid;
        int r = idx >> 3, w = idx & 7;
        cp16(smb + (uint32_t)(AQ_OFF + r*36 + w*4)*4, qb + (size_t)r*DH + w*8);
    }
    A_ISSUE(0);
    CP_COMMIT();

    float accO[8][4];
    #pragma unroll
    for (int nt = 0; nt < 8; nt++)
        #pragma unroll
        for (int r = 0; r < 4; r++) accO[nt][r] = 0.f;
    float mi[2] = {-INFINITY, -INFINITY};
    float li[2] = {0.f, 0.f};

    for (int kt = 0; kt < 32; kt++) {
        const int tb = kt % 3;

        if (kt + 1 < 32) A_ISSUE(kt + 1);
        CP_COMMIT();
        CP_WAIT1();
        __syncthreads();

        float s[8][4];
        #pragma unroll
        for (int nt = 0; nt < 8; nt++)
            #pragma unroll
            for (int r = 0; r < 4; r++) s[nt][r] = 0.f;

        const uint32_t Qb = smb + (uint32_t)(AQ_OFF + (m0 + a_row)*36)*4;
        const uint32_t Kb = smb + (uint32_t)(AK_OFF + tb*64*36)*4;
        #pragma unroll
        for (int ks = 0; ks < 4; ks++) {
            const int kb8 = ks * 8;
            uint32_t af[4];
            ldsm_x4(af, Qb + (uint32_t)(kb8 + a_kw)*4);
            #pragma unroll
            for (int j = 0; j < 4; j++) {
                uint32_t bf[4];
                ldsm_x4(bf, Kb + (uint32_t)((j*16 + b_row)*36 + kb8 + b_kw)*4);
                mma_f16(s[2*j],   af, bf[0], bf[1]);
                mma_f16(s[2*j+1], af, bf[2], bf[3]);
            }
        }

        const int* mk = (const int*)(sm + AM_OFF + tb*64);
        #pragma unroll
        for (int nt = 0; nt < 8; nt++) {
            const int c0 = nt*8 + tig*2;
            if (mk[c0])     { s[nt][0] = -1e9f; s[nt][2] = -1e9f; }
            if (mk[c0 + 1]) { s[nt][1] = -1e9f; s[nt][3] = -1e9f; }
        }

        #pragma unroll
        for (int half_ = 0; half_ < 2; half_++) {
            float rm = -INFINITY;
            #pragma unroll
            for (int nt = 0; nt < 8; nt++)
                rm = fmaxf(rm, fmaxf(s[nt][half_*2], s[nt][half_*2+1]));
            rm = fmaxf(rm, __shfl_xor_sync(0xffffffffu, rm, 1));
            rm = fmaxf(rm, __shfl_xor_sync(0xffffffffu, rm, 2));
            const float newm = fmaxf(mi[half_], rm);
            const float corr = __expf(mi[half_] - newm);
            float rs = 0.f;
            #pragma unroll
            for (int nt = 0; nt < 8; nt++) {
                s[nt][half_*2]   = __expf(s[nt][half_*2]   - newm);
                s[nt][half_*2+1] = __expf(s[nt][half_*2+1] - newm);
                rs += s[nt][half_*2] + s[nt][half_*2+1];
            }
            rs += __shfl_xor_sync(0xffffffffu, rs, 1);
            rs += __shfl_xor_sync(0xffffffffu, rs, 2);
            li[half_] = li[half_] * corr + rs;
            mi[half_] = newm;
            #pragma unroll
            for (int nt = 0; nt < 8; nt++) {
                accO[nt][half_*2]   *= corr;
                accO[nt][half_*2+1] *= corr;
            }
        }

        uint32_t* Pw = sm + AP_OFF;
        #pragma unroll
        for (int nt = 0; nt < 8; nt++) {
            const int wd = nt*4 + tig;
            Pw[(m0 + gid    )*36 + wd] = pack2(s[nt][0], s[nt][1]);
            Pw[(m0 + gid + 8)*36 + wd] = pack2(s[nt][2], s[nt][3]);
        }
        __syncthreads();

        const uint32_t Pb = smb + (uint32_t)(AP_OFF + (m0 + a_row)*36)*4;
        const uint32_t Vb = smb + (uint32_t)(AV_OFF + tb*64*36)*4;
        #pragma unroll
        for (int ks = 0; ks < 4; ks++) {
            const int kb8 = ks * 8;
            uint32_t af[4];
            ldsm_x4(af, Pb + (uint32_t)(kb8 + a_kw)*4);
            #pragma unroll
            for (int j = 0; j < 4; j++) {
                uint32_t bf[4];
                ldsm_x4(bf, Vb + (uint32_t)((j*16 + b_row)*36 + kb8 + b_kw)*4);
                mma_f16(accO[2*j],   af, bf[0], bf[1]);
                mma_f16(accO[2*j+1], af, bf[2], bf[3]);
            }
        }
    }
    #undef A_ISSUE

    const float inv0 = 1.f / li[0];
    const float inv1 = 1.f / li[1];
    const int r0 = qt*128 + m0 + gid;
    const int r1 = r0 + 8;
    #pragma unroll
    for (int nt = 0; nt < 8; nt++) {
        const int c = h*DH + nt*8 + tig*2;
        *(uint32_t*)&g_ctx[((size_t)(b*LL + r0))*DD + c] =
            pack2(accO[nt][0]*inv0, accO[nt][1]*inv0);
        *(uint32_t*)&g_ctx[((size_t)(b*LL + r1))*DD + c] =
            pack2(accO[nt][2]*inv1, accO[nt][3]*inv1);
    }
}

// ---------------------------------------------------------------------------
extern "C" void kernel_launch(void* const* d_in, const int* in_sizes, int n_in,
                              void* d_out, int out_size)
{
    const float* x  = (const float*)d_in[0];
    const int* mask = (const int*)d_in[1];
    const float* wq = (const float*)d_in[2];
    const float* bq = (const float*)d_in[3];
    const float* wk = (const float*)d_in[4];
    const float* bk = (const float*)d_in[5];
    const float* wv = (const float*)d_in[6];
    const float* bv = (const float*)d_in[7];
    const float* wo = (const float*)d_in[8];
    const float* bo = (const float*)d_in[9];
    float* out = (float*)d_out;

    cudaFuncSetAttribute(gemm_f16, cudaFuncAttributeMaxDynamicSharedMemorySize,
                         GEMM_SMEM);
    cudaFuncSetAttribute(attn_f16, cudaFuncAttributeMaxDynamicSharedMemorySize,
                         ATTN_SMEM);

    const int ncvt = (int)(((size_t)MM*DD/4 + (size_t)DD*DD + 255) / 256);
    cvt_kernel<<<ncvt, 256>>>(x, wq, wk, wv, wo);

    // merged QKV: N = 3072
    dim3 gqkv(3*DD/128, MM/128);   // 24 x 64 blocks
    gemm_f16<<<gqkv, 256, GEMM_SMEM>>>(bq, bk, bv, nullptr, 0);

    dim3 ga(LL/128, HH, BB);       // 16 x 16 x 4 blocks
    attn_f16<<<ga, 256, ATTN_SMEM>>>(mask);

    dim3 go(DD/128, MM/128);       // 8 x 64 blocks
    gemm_f16<<<go, 256, GEMM_SMEM>>>(bo, nullptr, nullptr, out, 3);
}

// round 9
// speedup vs baseline: 6.2596x; 1.0165x over previous
#include <cuda_runtime.h>
#include <cuda_fp16.h>
#include <math.h>
#include <stdint.h>

#define BB   4
#define HH   16
#define LL   2048
#define DD   1024
#define DH   64
#define MM   (BB*LL)   // 8192 tokens

// Scratch (device globals: allocation-free, graph-capturable). All fp16.
__device__ __half g_q[(size_t)BB*HH*LL*DH];    // (B,H,L,dh), pre-scaled by 0.125
__device__ __half g_k[(size_t)BB*HH*LL*DH];    // (B,H,L,dh)
__device__ __half g_v[(size_t)BB*HH*DH*LL];    // (B,H,dh,L)  TRANSPOSED
__device__ __half g_ctx[(size_t)MM*DD];        // (B,L,D)
__device__ __half g_xt[(size_t)MM*DD];         // x in fp16
__device__ __half g_wt[(size_t)4*DD*DD];       // wq,wk,wv,wo in fp16 (contiguous!)

// ---------------- helpers ----------------
__device__ __forceinline__ void mma_f16(float c[4], const uint32_t a[4],
                                        uint32_t b0, uint32_t b1) {
    asm volatile(
        "mma.sync.aligned.m16n8k16.row.col.f32.f16.f16.f32 "
        "{%0,%1,%2,%3}, {%4,%5,%6,%7}, {%8,%9}, {%0,%1,%2,%3};"
        : "+f"(c[0]), "+f"(c[1]), "+f"(c[2]), "+f"(c[3])
        : "r"(a[0]), "r"(a[1]), "r"(a[2]), "r"(a[3]), "r"(b0), "r"(b1));
}
__device__ __forceinline__ void ldsm_x4(uint32_t r[4], uint32_t saddr) {
    asm volatile("ldmatrix.sync.aligned.m8n8.x4.shared.b16 {%0,%1,%2,%3}, [%4];"
                 : "=r"(r[0]), "=r"(r[1]), "=r"(r[2]), "=r"(r[3]) : "r"(saddr));
}
__device__ __forceinline__ void cp16(uint32_t saddr, const void* gptr) {
    asm volatile("cp.async.cg.shared.global [%0], [%1], 16;"
                 :: "r"(saddr), "l"(gptr));
}
#define CP_COMMIT() asm volatile("cp.async.commit_group;")
#define CP_WAIT2()  asm volatile("cp.async.wait_group 2;")
#define CP_WAIT3()  asm volatile("cp.async.wait_group 3;")

__device__ __forceinline__ uint32_t pack2(float a, float b) {
    __half2 h = __floats2half2_rn(a, b);
    return *reinterpret_cast<uint32_t*>(&h);
}
__device__ __forceinline__ uint32_t smem_u32(const void* p) {
    uint32_t a;
    asm("{ .reg .u64 t; cvta.to.shared.u64 t, %1; cvt.u32.u64 %0, t; }"
        : "=r"(a) : "l"(p));
    return a;
}

// ---------------------------------------------------------------------------
// Convert x and the 4 weights to fp16.
// ---------------------------------------------------------------------------
__global__ void __launch_bounds__(256) cvt_kernel(
    const float* __restrict__ x,
    const float* __restrict__ wq, const float* __restrict__ wk,
    const float* __restrict__ wv, const float* __restrict__ wo)
{
    const size_t NX = (size_t)MM * DD / 4;
    const size_t NW = (size_t)DD * DD / 4;
    size_t i = (size_t)blockIdx.x * blockDim.x + threadIdx.x;
    if (i >= NX + 4 * NW) return;
    const float* src;
    __half* dst;
    size_t off;
    if (i < NX) { src = x; dst = g_xt; off = i; }
    else {
        size_t j = i - NX;
        int w = (int)(j / NW);
        off = j % NW;
        src = (w == 0) ? wq : (w == 1) ? wk : (w == 2) ? wv : wo;
        dst = g_wt + (size_t)w * DD * DD;
    }
    float4 v = ((const float4*)src)[off];
    ((__half2*)dst)[off*2]   = __floats2half2_rn(v.x, v.y);
    ((__half2*)dst)[off*2+1] = __floats2half2_rn(v.z, v.w);
}

// ---------------------------------------------------------------------------
// fp16 GEMM: 128x128 tile, 256 threads (8 warps as 2x4, each 64x32 tile),
// BK=32, 5-stage cp.async ring (prefetch distance 3), ldmatrix.x4 loads,
// 1 barrier/iter.
// out[m,n] = sum_k A[m,k]*W[n,k] + bias[n]
// mode 0: MERGED QKV (N=3072): bn>>10 selects q/k/v routing
//         (q scaled 0.125, v stored transposed (B,H,dh,L))
// mode 3: A=g_ctx, W=wo, plain fp32 out (M,N)
// smem: 5 stages x (A 128x20w + B 128x20w) = 102400 B -> 2 CTAs/SM.
// ---------------------------------------------------------------------------
#define GROW 20
#define GSTW (2*128*GROW)           // words per stage
#define GSTAGES 5
#define GEMM_SMEM (GSTAGES*GSTW*4)

__global__ void __launch_bounds__(256, 2) gemm_f16(
    const float* __restrict__ bq_, const float* __restrict__ bk_,
    const float* __restrict__ bv_, float* __restrict__ Oext,
    int mode)
{
    const __half* A = (mode == 3) ? g_ctx : g_xt;
    const __half* W = (mode == 3) ? (g_wt + (size_t)3*DD*DD) : g_wt;

    extern __shared__ uint32_t sm[];

    const int tid  = threadIdx.x;
    const int wid  = tid >> 5;
    const int lane = tid & 31;
    const int gid  = lane >> 2;
    const int tig  = lane & 3;
    const int warp_m = (wid & 1) * 64;
    const int warp_n = (wid >> 1) * 32;
    const int bm = blockIdx.y * 128;
    const int bn = blockIdx.x * 128;

    // loader: thread tid -> matrix (tid>>7), row (tid&127), 32 halfs
    const int lmat = tid >> 7;
    const int lrow = tid & 127;
    const __half* grow = lmat ? (W + (size_t)(bn + lrow) * DD)
                              : (A + (size_t)(bm + lrow) * DD);
    const uint32_t smb = smem_u32(sm);
    const uint32_t ldst = smb + (uint32_t)(lmat*128 + lrow) * GROW * 4;

    // ldmatrix per-lane addressing
    const int g  = lane >> 3;
    const int rr = lane & 7;
    const int a_row = warp_m + (g & 1) * 8 + rr;     // + mt*16
    const int a_kw  = (g >> 1) * 4;                  // + kb
    const int b_row = warp_n + (g >> 1) * 8 + rr;    // + j*16
    const int b_kw  = (g & 1) * 4;                   // + kb

    float acc[4][4][4];
    #pragma unroll
    for (int mt = 0; mt < 4; mt++)
        #pragma unroll
        for (int nt = 0; nt < 4; nt++)
            #pragma unroll
            for (int r = 0; r < 4; r++) acc[mt][nt][r] = 0.f;

    #define G_ISSUE(t_) do { \
        uint32_t d_ = ldst + (uint32_t)((t_) % GSTAGES) * GSTW * 4; \
        const __half* s_ = grow + (t_) * 32; \
        cp16(d_,      s_);      cp16(d_ + 16, s_ + 8); \
        cp16(d_ + 32, s_ + 16); cp16(d_ + 48, s_ + 24); \
    } while (0)

    G_ISSUE(0); CP_COMMIT();
    G_ISSUE(1); CP_COMMIT();
    G_ISSUE(2); CP_COMMIT();

    for (int i = 0; i < 32; i++) {
        if (i + 3 < 32) G_ISSUE(i + 3);
        CP_COMMIT();
        CP_WAIT3();
        __syncthreads();

        const uint32_t Ab = smb + (uint32_t)(i % GSTAGES) * GSTW * 4;
        const uint32_t Bb = Ab + 128 * GROW * 4;

        #pragma unroll
        for (int ks = 0; ks < 2; ks++) {
            const int kb = ks * 8;
            uint32_t af[4][4];
            #pragma unroll
            for (int mt = 0; mt < 4; mt++)
                ldsm_x4(af[mt], Ab + (uint32_t)((a_row + mt*16)*GROW + kb + a_kw)*4);
            #pragma unroll
            for (int j = 0; j < 2; j++) {
                uint32_t bf[4];
                ldsm_x4(bf, Bb + (uint32_t)((b_row + j*16)*GROW + kb + b_kw)*4);
                #pragma unroll
                for (int mt = 0; mt < 4; mt++) {
                    mma_f16(acc[mt][2*j],   af[mt], bf[0], bf[1]);
                    mma_f16(acc[mt][2*j+1], af[mt], bf[2], bf[3]);
                }
            }
        }
    }
    #undef G_ISSUE

    // epilogue
    const int which = (mode == 3) ? 3 : (bn >> 10);
    const float* bias = (which == 0) ? bq_ : (which == 1) ? bk_ : bv_;
    const float sc = (which == 0) ? 0.125f : 1.f;

    #pragma unroll
    for (int mt = 0; mt < 4; mt++) {
        #pragma unroll
        for (int nt = 0; nt < 4; nt++) {
            const int col = bn + warp_n + nt*8 + tig*2;   // global N col
            const int lc  = col & 1023;                    // local within matrix
            const float b0 = (mode == 3) ? bq_[lc] : bias[lc];
            const float b1 = (mode == 3) ? bq_[lc+1] : bias[lc+1];
            #pragma unroll
            for (int half_ = 0; half_ < 2; half_++) {
                const int m = bm + warp_m + mt*16 + gid + half_*8;
                float vx = (acc[mt][nt][half_*2 + 0] + b0) * sc;
                float vy = (acc[mt][nt][half_*2 + 1] + b1) * sc;
                if (mode == 3) {
                    *(float2*)&Oext[(size_t)m * DD + lc] = make_float2(vx, vy);
                } else {
                    const int bb = m >> 11;
                    const int ll = m & (LL - 1);
                    const int h  = lc >> 6;
                    const int c  = lc & (DH - 1);
                    if (which == 2) {   // V transposed: (B,H,dh,L)
                        const size_t base = ((size_t)(bb*HH + h)) * DH * LL;
                        g_v[base + (size_t)c    *LL + ll] = __float2half_rn(vx);
                        g_v[base + (size_t)(c+1)*LL + ll] = __float2half_rn(vy);
                    } else {
                        __half* dst = (which == 0) ? g_q : g_k;
                        *(uint32_t*)&dst[(((size_t)(bb*HH + h)*LL) + ll)*DH + c] =
                            pack2(vx, vy);
                    }
                }
            }
        }
    }
}

// ---------------------------------------------------------------------------
// fp16 flash attention: 128-query tile, 256 threads (8 warps x 16 q rows),
// 32 key tiles of 64. K/V/mask in 4-slot ring, prefetch distance 2,
// 1 CTA barrier per key tile (P is warp-private: __syncwarp only).
// V arrives pre-transposed [dh][L].
// ---------------------------------------------------------------------------
#define AQ_OFF 0
#define AP_OFF (128*36)
#define AK_OFF (2*128*36)
#define AV_OFF (AK_OFF + 4*64*36)
#define AM_OFF (AV_OFF + 4*64*36)
#define ATTN_SMEM ((AM_OFF + 4*64)*4)

__global__ void __launch_bounds__(256, 2) attn_f16(const int* __restrict__ mask)
{
    extern __shared__ uint32_t sm[];

    const int qt  = blockIdx.x;
    const int h   = blockIdx.y;
    const int b   = blockIdx.z;
    const int tid = threadIdx.x;
    const int wid = tid >> 5;
    const int lane = tid & 31;
    const int gid = lane >> 2;
    const int tig = lane & 3;
    const int m0  = wid * 16;

    const __half* qb = g_q + ((size_t)(b*HH + h))*LL*DH + (size_t)qt*128*DH;
    const __half* kb = g_k + ((size_t)(b*HH + h))*LL*DH;
    const __half* vb = g_v + ((size_t)(b*HH + h))*DH*LL;
    const int* mrow = mask + (size_t)b * LL;
    const uint32_t smb = smem_u32(sm);

    const int g  = lane >> 3;
    const int rr = lane & 7;
    const int a_row = (g & 1) * 8 + rr;
    const int a_kw  = (g >> 1) * 4;
    const int b_row = (g >> 1) * 8 + rr;
    const int b_kw  = (g & 1) * 4;

    #define A_ISSUE(kt_) do { \
        const int tb_ = (kt_) & 3; \
        const __half* ksrc_ = kb + (size_t)(kt_)*64*DH; \
        _Pragma("unroll") \
        for (int rep_ = 0; rep_ < 2; rep_++) { \
            int idx_ = rep_*256 + tid; \
            int r_ = idx_ >> 3, w_ = (idx_ & 7); \
            cp16(smb + (uint32_t)(AK_OFF + tb_*64*36 + r_*36 + w_*4)*4, \
                 ksrc_ + (size_t)r_*DH + w_*8); \
            cp16(smb + (uint32_t)(AV_OFF + tb_*64*36 + r_*36 + w_*4)*4, \
                 vb + (size_t)r_*LL + (kt_)*64 + w_*8); \
        } \
        if (tid < 16) cp16(smb + (uint32_t)(AM_OFF + tb_*64 + tid*4)*4, \
                           mrow + (kt_)*64 + tid*4); \
    } while (0)

    // prologue: Q + tile 0 in group 0; tile 1 in group 1
    #pragma unroll
    for (int rep = 0; rep < 4; rep++) {
        int idx = rep*256 + tid;
        int r = idx >> 3, w = idx & 7;
        cp16(smb + (uint32_t)(AQ_OFF + r*36 + w*4)*4, qb + (size_t)r*DH + w*8);
    }
    A_ISSUE(0);
    CP_COMMIT();
    A_ISSUE(1);
    CP_COMMIT();

    float accO[8][4];
    #pragma unroll
    for (int nt = 0; nt < 8; nt++)
        #pragma unroll
        for (int r = 0; r < 4; r++) accO[nt][r] = 0.f;
    float mi[2] = {-INFINITY, -INFINITY};
    float li[2] = {0.f, 0.f};

    for (int kt = 0; kt < 32; kt++) {
        const int tb = kt & 3;

        if (kt + 2 < 32) A_ISSUE(kt + 2);
        CP_COMMIT();
        CP_WAIT2();
        __syncthreads();

        // S = Q K^T  (Q pre-scaled by 0.125)
        float s[8][4];
        #pragma unroll
        for (int nt = 0; nt < 8; nt++)
            #pragma unroll
            for (int r = 0; r < 4; r++) s[nt][r] = 0.f;

        const uint32_t Qb = smb + (uint32_t)(AQ_OFF + (m0 + a_row)*36)*4;
        const uint32_t Kb = smb + (uint32_t)(AK_OFF + tb*64*36)*4;
        #pragma unroll
        for (int ks = 0; ks < 4; ks++) {
            const int kb8 = ks * 8;
            uint32_t af[4];
            ldsm_x4(af, Qb + (uint32_t)(kb8 + a_kw)*4);
            #pragma unroll
            for (int j = 0; j < 4; j++) {
                uint32_t bf[4];
                ldsm_x4(bf, Kb + (uint32_t)((j*16 + b_row)*36 + kb8 + b_kw)*4);
                mma_f16(s[2*j],   af, bf[0], bf[1]);
                mma_f16(s[2*j+1], af, bf[2], bf[3]);
            }
        }

        // mask (exact -1e9, scale already in Q)
        const int* mk = (const int*)(sm + AM_OFF + tb*64);
        #pragma unroll
        for (int nt = 0; nt < 8; nt++) {
            const int c0 = nt*8 + tig*2;
            if (mk[c0])     { s[nt][0] = -1e9f; s[nt][2] = -1e9f; }
            if (mk[c0 + 1]) { s[nt][1] = -1e9f; s[nt][3] = -1e9f; }
        }

        // online softmax (rows gid, gid+8)
        #pragma unroll
        for (int half_ = 0; half_ < 2; half_++) {
            float rm = -INFINITY;
            #pragma unroll
            for (int nt = 0; nt < 8; nt++)
                rm = fmaxf(rm, fmaxf(s[nt][half_*2], s[nt][half_*2+1]));
            rm = fmaxf(rm, __shfl_xor_sync(0xffffffffu, rm, 1));
            rm = fmaxf(rm, __shfl_xor_sync(0xffffffffu, rm, 2));
            const float newm = fmaxf(mi[half_], rm);
            const float corr = __expf(mi[half_] - newm);
            float rs = 0.f;
            #pragma unroll
            for (int nt = 0; nt < 8; nt++) {
                s[nt][half_*2]   = __expf(s[nt][half_*2]   - newm);
                s[nt][half_*2+1] = __expf(s[nt][half_*2+1] - newm);
                rs += s[nt][half_*2] + s[nt][half_*2+1];
            }
            rs += __shfl_xor_sync(0xffffffffu, rs, 1);
            rs += __shfl_xor_sync(0xffffffffu, rs, 2);
            li[half_] = li[half_] * corr + rs;
            mi[half_] = newm;
            #pragma unroll
            for (int nt = 0; nt < 8; nt++) {
                accO[nt][half_*2]   *= corr;
                accO[nt][half_*2+1] *= corr;
            }
        }

        // store P (fp16 pairs) — warp-private rows, so only __syncwarp needed
        uint32_t* Pw = sm + AP_OFF;
        #pragma unroll
        for (int nt = 0; nt < 8; nt++) {
            const int wd = nt*4 + tig;
            Pw[(m0 + gid    )*36 + wd] = pack2(s[nt][0], s[nt][1]);
            Pw[(m0 + gid + 8)*36 + wd] = pack2(s[nt][2], s[nt][3]);
        }
        __syncwarp();

        // O += P @ V   (V rows = dh, words = key pairs)
        const uint32_t Pb = smb + (uint32_t)(AP_OFF + (m0 + a_row)*36)*4;
        const uint32_t Vb = smb + (uint32_t)(AV_OFF + tb*64*36)*4;
        #pragma unroll
        for (int ks = 0; ks < 4; ks++) {
            const int kb8 = ks * 8;
            uint32_t af[4];
            ldsm_x4(af, Pb + (uint32_t)(kb8 + a_kw)*4);
            #pragma unroll
            for (int j = 0; j < 4; j++) {
                uint32_t bf[4];
                ldsm_x4(bf, Vb + (uint32_t)((j*16 + b_row)*36 + kb8 + b_kw)*4);
                mma_f16(accO[2*j],   af, bf[0], bf[1]);
                mma_f16(accO[2*j+1], af, bf[2], bf[3]);
            }
        }
    }
    #undef A_ISSUE

    const float inv0 = 1.f / li[0];
    const float inv1 = 1.f / li[1];
    const int r0 = qt*128 + m0 + gid;
    const int r1 = r0 + 8;
    #pragma unroll
    for (int nt = 0; nt < 8; nt++) {
        const int c = h*DH + nt*8 + tig*2;
        *(uint32_t*)&g_ctx[((size_t)(b*LL + r0))*DD + c] =
            pack2(accO[nt][0]*inv0, accO[nt][1]*inv0);
        *(uint32_t*)&g_ctx[((size_t)(b*LL + r1))*DD + c] =
            pack2(accO[nt][2]*inv1, accO[nt][3]*inv1);
    }
}

// ---------------------------------------------------------------------------
extern "C" void kernel_launch(void* const* d_in, const int* in_sizes, int n_in,
                              void* d_out, int out_size)
{
    const float* x  = (const float*)d_in[0];
    const int* mask = (const int*)d_in[1];
    const float* wq = (const float*)d_in[2];
    const float* bq = (const float*)d_in[3];
    const float* wk = (const float*)d_in[4];
    const float* bk = (const float*)d_in[5];
    const float* wv = (const float*)d_in[6];
    const float* bv = (const float*)d_in[7];
    const float* wo = (const float*)d_in[8];
    const float* bo = (const float*)d_in[9];
    float* out = (float*)d_out;

    cudaFuncSetAttribute(gemm_f16, cudaFuncAttributeMaxDynamicSharedMemorySize,
                         GEMM_SMEM);
    cudaFuncSetAttribute(attn_f16, cudaFuncAttributeMaxDynamicSharedMemorySize,
                         ATTN_SMEM);

    const int ncvt = (int)(((size_t)MM*DD/4 + (size_t)DD*DD + 255) / 256);
    cvt_kernel<<<ncvt, 256>>>(x, wq, wk, wv, wo);

    // merged QKV: N = 3072
    dim3 gqkv(3*DD/128, MM/128);   // 24 x 64 blocks
    gemm_f16<<<gqkv, 256, GEMM_SMEM>>>(bq, bk, bv, nullptr, 0);

    dim3 ga(LL/128, HH, BB);       // 16 x 16 x 4 blocks
    attn_f16<<<ga, 256, ATTN_SMEM>>>(mask);

    dim3 go(DD/128, MM/128);       // 8 x 64 blocks
    gemm_f16<<<go, 256, GEMM_SMEM>>>(bo, nullptr, nullptr, out, 3);
}